// round 13
// baseline (speedup 1.0000x reference)
#include <cuda_runtime.h>
#include <cuda_bf16.h>
#include <math.h>
#include <stdint.h>

#define DINL __device__ __forceinline__
#define B_   256
#define N_   400
#define H_   512
#define E_   256
#define V_   50000
#define OOV_ 50
#define T_   49

// -------- device scratch (allocation-free) --------
__device__ float g_x[B_ * E_];
__device__ float g_gates[B_ * 4 * H_];
__device__ float g_sthat[B_ * 2 * H_];
__device__ float g_bias_e[B_ * 2 * H_];
__device__ float g_bias_d[B_ * H_];
__device__ float g_et_part[B_ * N_ * 8];
__device__ float g_at[B_ * N_];
__device__ float g_etd_part[B_ * T_ * 4];
__device__ float g_ctd[B_ * H_];
__device__ float g_pgen[B_];
__device__ float g_outfeat[B_ * H_];
__device__ float g_logits[(size_t)B_ * V_];
__device__ float g_rmax[B_];
__device__ float g_rsum[B_];
__device__ __nv_bfloat16 g_bbf[1024 * 1024];          // Whw bf16
__device__ __nv_bfloat16 g_wpbf[512 * 512];           // Wprev bf16
__device__ __nv_bfloat16 g_v1bf[(size_t)V_ * H_];     // V1 bf16

DINL unsigned pack_bf16(float x, float y) {
    __nv_bfloat162 h = __floats2bfloat162_rn(x, y);
    return *reinterpret_cast<unsigned*>(&h);
}
DINL void mma16816(float* d, const unsigned* a, const unsigned* b, const float* c) {
    asm volatile(
        "mma.sync.aligned.m16n8k16.row.col.f32.bf16.bf16.f32 "
        "{%0,%1,%2,%3}, {%4,%5,%6,%7}, {%8,%9}, {%10,%11,%12,%13};\n"
        : "=f"(d[0]), "=f"(d[1]), "=f"(d[2]), "=f"(d[3])
        : "r"(a[0]), "r"(a[1]), "r"(a[2]), "r"(a[3]), "r"(b[0]), "r"(b[1]),
          "f"(c[0]), "f"(c[1]), "f"(c[2]), "f"(c[3]));
}
DINL float sigm(float v) { return 1.f / (1.f + expf(-v)); }
DINL uint32_t smem_u32(const void* p) {
    uint32_t a;
    asm("{ .reg .u64 t; cvta.to.shared.u64 t, %1; cvt.u32.u64 %0, t; }" : "=r"(a) : "l"(p));
    return a;
}
#define LDSM4(r0, r1, r2, r3, addr) \
    asm volatile("ldmatrix.sync.aligned.m8n8.x4.shared.b16 {%0,%1,%2,%3}, [%4];" \
        : "=r"(r0), "=r"(r1), "=r"(r2), "=r"(r3) : "r"(addr))
#define CPA16(dst, src) \
    asm volatile("cp.async.cg.shared.global [%0], [%1], 16;" :: "r"(dst), "l"(src))
#define CPA_COMMIT() asm volatile("cp.async.commit_group;" ::: "memory")
#define CPA_WAIT0()  asm volatile("cp.async.wait_group 0;" ::: "memory")

DINL float4 cat3_v4(const float* p0, int w0, const float* p1, int w1,
                    const float* p2, int w2, int row, int k) {
    if (k < w0) return *(const float4*)(p0 + (size_t)row * w0 + k);
    k -= w0;
    if (k < w1) return *(const float4*)(p1 + (size_t)row * w1 + k);
    return *(const float4*)(p2 + (size_t)row * w2 + (k - w1));
}
DINL float4 cat2w_v4(const float* p0, int w0, const float* p1, int w1, int row, int k) {
    if (k < w0) return *(const float4*)(p0 + (size_t)row * w0 + k);
    return *(const float4*)(p1 + (size_t)row * w1 + (k - w0));
}

// ===== exact fp32 GEMM (R10-validated) =====
__global__ __launch_bounds__(256)
void sgemm2(const float* a0, int aw0, const float* a1, int aw1,
            const float* a2, int aw2,
            const float* w0, int ww0, const float* w1, int ww1,
            const float* b0, const float* b1,
            float* __restrict__ C, int M, int Nc, int K) {
    __shared__ float As[32][68];
    __shared__ float Ws[32][68];
    const int tid = threadIdx.x;
    const int n0 = blockIdx.x * 64, m0 = blockIdx.y * 64;
    const int lm  = tid & 63;
    const int lk4 = (tid >> 6) * 4;
    const int tx = tid & 15, ty = tid >> 4;

    float4 ra[2], rw[2];
    ra[0] = cat3_v4(a0, aw0, a1, aw1, a2, aw2, m0 + lm, lk4);
    ra[1] = cat3_v4(a0, aw0, a1, aw1, a2, aw2, m0 + lm, lk4 + 16);
    rw[0] = cat2w_v4(w0, ww0, w1, ww1, n0 + lm, lk4);
    rw[1] = cat2w_v4(w0, ww0, w1, ww1, n0 + lm, lk4 + 16);

    float acc[4][4];
#pragma unroll
    for (int i = 0; i < 4; i++)
#pragma unroll
        for (int j = 0; j < 4; j++) acc[i][j] = 0.f;

    for (int k0 = 0; k0 < K; k0 += 32) {
#pragma unroll
        for (int h = 0; h < 2; h++) {
            int kb = lk4 + h * 16;
            As[kb + 0][lm] = ra[h].x; As[kb + 1][lm] = ra[h].y;
            As[kb + 2][lm] = ra[h].z; As[kb + 3][lm] = ra[h].w;
            Ws[kb + 0][lm] = rw[h].x; Ws[kb + 1][lm] = rw[h].y;
            Ws[kb + 2][lm] = rw[h].z; Ws[kb + 3][lm] = rw[h].w;
        }
        __syncthreads();
        if (k0 + 32 < K) {
            ra[0] = cat3_v4(a0, aw0, a1, aw1, a2, aw2, m0 + lm, k0 + 32 + lk4);
            ra[1] = cat3_v4(a0, aw0, a1, aw1, a2, aw2, m0 + lm, k0 + 32 + lk4 + 16);
            rw[0] = cat2w_v4(w0, ww0, w1, ww1, n0 + lm, k0 + 32 + lk4);
            rw[1] = cat2w_v4(w0, ww0, w1, ww1, n0 + lm, k0 + 32 + lk4 + 16);
        }
#pragma unroll
        for (int kk = 0; kk < 32; kk++) {
            float4 av = *(const float4*)&As[kk][ty * 4];
            float4 bv = *(const float4*)&Ws[kk][tx * 4];
            acc[0][0] += av.x * bv.x; acc[0][1] += av.x * bv.y;
            acc[0][2] += av.x * bv.z; acc[0][3] += av.x * bv.w;
            acc[1][0] += av.y * bv.x; acc[1][1] += av.y * bv.y;
            acc[1][2] += av.y * bv.z; acc[1][3] += av.y * bv.w;
            acc[2][0] += av.z * bv.x; acc[2][1] += av.z * bv.y;
            acc[2][2] += av.z * bv.z; acc[2][3] += av.z * bv.w;
            acc[3][0] += av.w * bv.x; acc[3][1] += av.w * bv.y;
            acc[3][2] += av.w * bv.z; acc[3][3] += av.w * bv.w;
        }
        __syncthreads();
    }
#pragma unroll
    for (int i = 0; i < 4; i++) {
        int row = m0 + ty * 4 + i;
#pragma unroll
        for (int j = 0; j < 4; j++) {
            int col = n0 + tx * 4 + j;
            C[(size_t)row * Nc + col] = acc[i][j] + b0[col] + (b1 ? b1[col] : 0.f);
        }
    }
}

// ===== fp32 -> bf16 pre-convert =====
__global__ void conv_bf16(const float* __restrict__ src, __nv_bfloat16* __restrict__ dst) {
    size_t i = ((size_t)blockIdx.x * 256 + threadIdx.x) * 8;
    float4 a = *(const float4*)(src + i), b = *(const float4*)(src + i + 4);
    uint4 o;
    o.x = pack_bf16(a.x, a.y); o.y = pack_bf16(a.z, a.w);
    o.z = pack_bf16(b.x, b.y); o.w = pack_bf16(b.z, b.w);
    *(uint4*)(dst + i) = o;
}

// ===== tensor-core GEMM v3: 128x128 tile, 64x32/warp, 2 CTAs/SM =====
// C = A[M,KDIM](fp32) @ Bb[Ncols,KDIM](bf16)^T
// MODE 0: out[m*gridDim.x + bx] = sum_col tanh(acc+bias[r/TOK][col])*v[col]
// MODE 1: out[m*Ncols+col] = acc + bias[col]   (col guarded)
// smem/stage: A 128x32 bf16 stride 80 (10240) + B 128x32 bf16 stride 80 (10240)
#define M3_STAGE 20480
#define M3_SMEM  (2 * M3_STAGE)

template <int MODE, int KDIM, int TOK>
__global__ __launch_bounds__(256, 2)
void mma3(const float* __restrict__ A, const __nv_bfloat16* __restrict__ Bb,
          const float* __restrict__ bias, const float* __restrict__ vvec,
          float* __restrict__ out, int Ncols) {
    extern __shared__ char smem[];
    const uint32_t sbu = smem_u32(smem);
    const int tid = threadIdx.x, lane = tid & 31, warp = tid >> 5;
    const int wm = warp >> 2, wn = warp & 3;          // 2 x 4 warp grid -> 64x32 tiles
    const int n0 = blockIdx.x * 128;
    const long m0 = (long)blockIdx.y * 128;
    const int arow = tid & 127, ahalf = tid >> 7;
    const int KT = KDIM / 32;

    float acc[4][4][4];
#pragma unroll
    for (int i = 0; i < 4; i++)
#pragma unroll
        for (int j = 0; j < 4; j++)
#pragma unroll
            for (int c = 0; c < 4; c++) acc[i][j][c] = 0.f;

    const float* aRow = A + (size_t)(m0 + arow) * KDIM + ahalf * 16;
    float4 ar[4];

    // B stage: 128 rows x 64B -> 512 x 16B segs; 2 per thread
    auto cpB = [&](int kt, int buf) {
        uint32_t base = sbu + buf * M3_STAGE + 10240;
#pragma unroll
        for (int i = 0; i < 2; i++) {
            int c = tid + 256 * i;
            int row = c >> 2, seg = c & 3;
            int gr = n0 + row;
            if (MODE == 1 && gr >= Ncols) gr = 0;
            const __nv_bfloat16* src = Bb + (size_t)gr * KDIM + kt * 32 + seg * 8;
            CPA16(base + row * 80 + seg * 16, src);
        }
    };
    auto stsA = [&](int buf) {
        uint4 u0, u1;
        u0.x = pack_bf16(ar[0].x, ar[0].y); u0.y = pack_bf16(ar[0].z, ar[0].w);
        u0.z = pack_bf16(ar[1].x, ar[1].y); u0.w = pack_bf16(ar[1].z, ar[1].w);
        u1.x = pack_bf16(ar[2].x, ar[2].y); u1.y = pack_bf16(ar[2].z, ar[2].w);
        u1.z = pack_bf16(ar[3].x, ar[3].y); u1.w = pack_bf16(ar[3].z, ar[3].w);
        char* d = smem + buf * M3_STAGE + arow * 80 + ahalf * 32;
        *(uint4*)d = u0;
        *(uint4*)(d + 16) = u1;
    };

    const uint32_t a_lds = sbu + (wm * 64 + (lane & 15)) * 80 + (lane >> 4) * 16;
    const uint32_t b_lds = sbu + 10240 + (wn * 32 + (lane & 15)) * 80 + (lane >> 4) * 16;

    auto compute = [&](int buf) {
        uint32_t ab = a_lds + buf * M3_STAGE, bb = b_lds + buf * M3_STAGE;
#pragma unroll
        for (int s = 0; s < 2; s++) {
            unsigned af[4][4], bfr[4][2];
#pragma unroll
            for (int mi = 0; mi < 4; mi++)
                LDSM4(af[mi][0], af[mi][1], af[mi][2], af[mi][3], ab + mi * 1280 + s * 32);
#pragma unroll
            for (int p = 0; p < 2; p++) {
                unsigned r0, r1, r2, r3;
                LDSM4(r0, r1, r2, r3, bb + p * 1280 + s * 32);
                bfr[2 * p][0] = r0; bfr[2 * p][1] = r2;
                bfr[2 * p + 1][0] = r1; bfr[2 * p + 1][1] = r3;
            }
#pragma unroll
            for (int mi = 0; mi < 4; mi++)
#pragma unroll
                for (int ni = 0; ni < 4; ni++)
                    mma16816(acc[mi][ni], af[mi], bfr[ni], acc[mi][ni]);
        }
    };

    { const float4* ap = (const float4*)aRow;
      ar[0] = ap[0]; ar[1] = ap[1]; ar[2] = ap[2]; ar[3] = ap[3]; }
    cpB(0, 0); CPA_COMMIT();
    stsA(0);
    CPA_WAIT0(); __syncthreads();

    for (int kt = 0; kt < KT; kt++) {
        const int buf = kt & 1, nbuf = buf ^ 1;
        if (kt + 1 < KT) {
            const float4* ap = (const float4*)(aRow + (kt + 1) * 32);
            ar[0] = ap[0]; ar[1] = ap[1]; ar[2] = ap[2]; ar[3] = ap[3];
            cpB(kt + 1, nbuf); CPA_COMMIT();
        }
        compute(buf);
        __syncthreads();
        if (kt + 1 < KT) {
            stsA(nbuf);
            CPA_WAIT0();
            __syncthreads();
        }
    }

    if (MODE == 0) {
        float rs[4][2];
#pragma unroll
        for (int mi = 0; mi < 4; mi++) { rs[mi][0] = 0.f; rs[mi][1] = 0.f; }
#pragma unroll
        for (int mi = 0; mi < 4; mi++)
#pragma unroll
            for (int ni = 0; ni < 4; ni++)
#pragma unroll
                for (int c = 0; c < 4; c++) {
                    int col = wn * 32 + ni * 8 + (lane & 3) * 2 + (c & 1);
                    long r = m0 + wm * 64 + mi * 16 + (lane >> 2) + (c >> 1) * 8;
                    int bb2 = (int)(r / TOK);
                    float x = acc[mi][ni][c] + bias[(size_t)bb2 * Ncols + n0 + col];
                    x = fminf(fmaxf(x, -15.f), 15.f);
                    float e = __expf(2.f * x);
                    rs[mi][c >> 1] += __fdividef(e - 1.f, e + 1.f) * vvec[n0 + col];
                }
#pragma unroll
        for (int mi = 0; mi < 4; mi++)
#pragma unroll
            for (int h = 0; h < 2; h++) {
                rs[mi][h] += __shfl_xor_sync(0xffffffffu, rs[mi][h], 1);
                rs[mi][h] += __shfl_xor_sync(0xffffffffu, rs[mi][h], 2);
            }
        float* red = (float*)smem;
        __syncthreads();
        if ((lane & 3) == 0) {
#pragma unroll
            for (int mi = 0; mi < 4; mi++)
#pragma unroll
                for (int h = 0; h < 2; h++) {
                    int rl = wm * 64 + mi * 16 + (lane >> 2) + h * 8;
                    red[rl * 4 + wn] = rs[mi][h];
                }
        }
        __syncthreads();
        if (tid < 128)
            out[(m0 + tid) * gridDim.x + blockIdx.x] =
                red[tid * 4] + red[tid * 4 + 1] + red[tid * 4 + 2] + red[tid * 4 + 3];
    } else {
#pragma unroll
        for (int mi = 0; mi < 4; mi++)
#pragma unroll
            for (int ni = 0; ni < 4; ni++)
#pragma unroll
                for (int c = 0; c < 4; c++) {
                    int gcol = n0 + wn * 32 + ni * 8 + (lane & 3) * 2 + (c & 1);
                    long r = m0 + wm * 64 + mi * 16 + (lane >> 2) + (c >> 1) * 8;
                    if (gcol < Ncols)
                        out[(size_t)r * Ncols + gcol] = acc[mi][ni][c] + bias[gcol];
                }
    }
}

// ===== elementwise / reductions =====
__global__ void lstm_kernel(const float* __restrict__ dec_c,
                            float* __restrict__ o_h, float* __restrict__ o_c) {
    int idx = blockIdx.x * 256 + threadIdx.x;
    int b = idx >> 9, h = idx & 511;
    const float* g = g_gates + (size_t)b * 2048;
    float c  = sigm(g[512 + h]) * dec_c[idx] + sigm(g[h]) * tanhf(g[1024 + h]);
    float hn = sigm(g[1536 + h]) * tanhf(c);
    o_h[idx] = hn; o_c[idx] = c;
    g_sthat[(size_t)b * 1024 + h] = hn;
    g_sthat[(size_t)b * 1024 + 512 + h] = c;
}

__global__ void et_finalize(const float* __restrict__ sumt, const float* __restrict__ mask,
                            float* __restrict__ o_sum) {
    int b = blockIdx.x, n = threadIdx.x;   // 512 thr
    __shared__ float sh[512];
    float atv = 0.f;
    if (n < N_) {
        const float* p = g_et_part + (size_t)(b * N_ + n) * 8;
        float e = expf(p[0] + p[1] + p[2] + p[3] + p[4] + p[5] + p[6] + p[7]);
        float st = sumt[b * N_ + n];
        o_sum[b * N_ + n] = st + e;
        atv = (e / st) * mask[b * N_ + n];
    }
    sh[n] = atv; __syncthreads();
    for (int st = 256; st > 0; st >>= 1) { if (n < st) sh[n] += sh[n + st]; __syncthreads(); }
    if (n < N_) g_at[b * N_ + n] = atv / sh[0];
}

__global__ void ctx_enc(const float* __restrict__ enc, float* __restrict__ o_cte) {
    int b = blockIdx.x, t = threadIdx.x;   // 256 thr
    __shared__ float a_s[N_];
    for (int i = t; i < N_; i += 256) a_s[i] = g_at[b * N_ + i];
    __syncthreads();
    float4 acc = make_float4(0, 0, 0, 0);
    const float4* base = (const float4*)(enc + (size_t)b * N_ * 1024) + t;
#pragma unroll 4
    for (int n = 0; n < N_; ++n) {
        float4 v = base[(size_t)n * 256]; float w = a_s[n];
        acc.x += w * v.x; acc.y += w * v.y; acc.z += w * v.z; acc.w += w * v.w;
    }
    ((float4*)(o_cte + (size_t)b * 1024))[t] = acc;
}

__global__ void dec_attn_finalize(const float* __restrict__ prev_s,
                                  const float* __restrict__ h_new,
                                  float* __restrict__ o_prev) {
    int b = blockIdx.x, tid = threadIdx.x;  // 256 thr
    __shared__ float atd[T_];
    __shared__ float tot;
    if (tid < T_) {
        const float* p = g_etd_part + (size_t)(b * T_ + tid) * 4;
        atd[tid] = expf(p[0] + p[1] + p[2] + p[3]);
    }
    __syncthreads();
    if (tid == 0) { float s = 0.f; for (int i = 0; i < T_; ++i) s += atd[i]; tot = s; }
    __syncthreads();
    float inv = 1.f / tot;
#pragma unroll
    for (int cg = 0; cg < 2; ++cg) {
        int col = tid + cg * 256;
        float acc = 0.f;
        for (int t2 = 0; t2 < T_; ++t2)
            acc += atd[t2] * prev_s[((size_t)b * T_ + t2) * H_ + col];
        g_ctd[(size_t)b * H_ + col] = acc * inv;
    }
    for (int i = tid; i < T_ * H_; i += 256)
        o_prev[(size_t)b * (T_ + 1) * H_ + i] = prev_s[(size_t)b * T_ * H_ + i];
    for (int i = tid; i < H_; i += 256)
        o_prev[(size_t)b * (T_ + 1) * H_ + T_ * H_ + i] = h_new[(size_t)b * H_ + i];
}

__global__ void pgen_kernel(const float* __restrict__ cte,
                            const float* __restrict__ w, const float* __restrict__ bias) {
    int b = blockIdx.x, tid = threadIdx.x;  // 256 thr, K=2816
    float s = 0.f;
    for (int k = tid; k < 2816; k += 256) {
        float a;
        if (k < 1024)      a = cte[(size_t)b * 1024 + k];
        else if (k < 1536) a = g_ctd[(size_t)b * 512 + (k - 1024)];
        else if (k < 2560) a = g_sthat[(size_t)b * 1024 + (k - 1536)];
        else               a = g_x[(size_t)b * 256 + (k - 2560)];
        s += a * w[k];
    }
    __shared__ float sh[256];
    sh[tid] = s; __syncthreads();
    for (int st = 128; st > 0; st >>= 1) { if (tid < st) sh[tid] += sh[tid + st]; __syncthreads(); }
    if (tid == 0) g_pgen[b] = sigm(sh[0] + bias[0]);
}

__global__ void vocab_stats() {
    int b = blockIdx.x, tid = threadIdx.x;  // 512 thr
    const float* row = g_logits + (size_t)b * V_;
    __shared__ float sh[512];
    float m = -1e30f;
    for (int v = tid; v < V_; v += 512) m = fmaxf(m, row[v]);
    sh[tid] = m; __syncthreads();
    for (int st = 256; st > 0; st >>= 1) { if (tid < st) sh[tid] = fmaxf(sh[tid], sh[tid + st]); __syncthreads(); }
    float mx = sh[0]; __syncthreads();
    float s = 0.f;
    for (int v = tid; v < V_; v += 512) s += expf(row[v] - mx);
    sh[tid] = s; __syncthreads();
    for (int st = 256; st > 0; st >>= 1) { if (tid < st) sh[tid] += sh[tid + st]; __syncthreads(); }
    if (tid == 0) { g_rmax[b] = mx; g_rsum[b] = sh[0]; }
}

__global__ void final_dist_kernel(const int* __restrict__ idx, float* __restrict__ out) {
    int b = blockIdx.x, tid = threadIdx.x;  // 512 thr
    float pg = g_pgen[b], scale = pg / g_rsum[b], mx = g_rmax[b];
    float* row = out + (size_t)b * (V_ + OOV_);
    const float* lrow = g_logits + (size_t)b * V_;
    for (int v = tid; v < V_ + OOV_; v += 512)
        row[v] = (v < V_) ? expf(lrow[v] - mx) * scale : 0.f;
    __shared__ int   sidx[N_];
    __shared__ float sval[N_];
    float am = 1.f - pg;
    for (int n = tid; n < N_; n += 512) {
        sidx[n] = idx[b * N_ + n];
        sval[n] = am * g_at[b * N_ + n];
    }
    __syncthreads();
    if (tid < N_) {
        int my = sidx[tid];
        bool leader = true;
        for (int i = 0; i < tid; ++i) if (sidx[i] == my) { leader = false; break; }
        if (leader) {
            float s = 0.f;
            for (int i = tid; i < N_; ++i) if (sidx[i] == my) s += sval[i];
            row[my] += s;
        }
    }
}

// ===== host launcher =====
extern "C" void kernel_launch(void* const* d_in, const int* in_sizes, int n_in,
                              void* d_out, int out_size) {
    (void)in_sizes; (void)n_in; (void)out_size;
    const float* x_t       = (const float*)d_in[0];
    const float* dec_h     = (const float*)d_in[1];
    const float* dec_c     = (const float*)d_in[2];
    const float* enc_out   = (const float*)d_in[3];
    const float* enc_mask  = (const float*)d_in[4];
    const float* ct_e      = (const float*)d_in[5];
    const int*   ext_vocab = (const int*)  d_in[7];
    const float* sum_temp  = (const float*)d_in[8];
    const float* prev_s    = (const float*)d_in[9];
    const float* xw   = (const float*)d_in[10];
    const float* xb   = (const float*)d_in[11];
    const float* wih  = (const float*)d_in[12];
    const float* whh  = (const float*)d_in[13];
    const float* bih  = (const float*)d_in[14];
    const float* bhh  = (const float*)d_in[15];
    const float* pgw  = (const float*)d_in[16];
    const float* pgb  = (const float*)d_in[17];
    const float* Vw   = (const float*)d_in[18];
    const float* Vb   = (const float*)d_in[19];
    const float* V1w  = (const float*)d_in[20];
    const float* V1b  = (const float*)d_in[21];
    const float* Whw  = (const float*)d_in[22];
    const float* Wsw  = (const float*)d_in[23];
    const float* Wsb  = (const float*)d_in[24];
    const float* vw   = (const float*)d_in[25];
    const float* Wpw  = (const float*)d_in[26];
    const float* Wsdw = (const float*)d_in[27];
    const float* Wsdb = (const float*)d_in[28];
    const float* vdw  = (const float*)d_in[29];

    float* out = (float*)d_out;
    float* o_fd   = out;
    float* o_h    = out + (size_t)B_ * (V_ + OOV_);
    float* o_c    = o_h  + B_ * H_;
    float* o_cte  = o_c  + B_ * H_;
    float* o_sum  = o_cte + B_ * 2 * H_;
    float* o_prev = o_sum + B_ * N_;

    void* p;
    cudaGetSymbolAddress(&p, g_x);        float* px   = (float*)p;
    cudaGetSymbolAddress(&p, g_gates);    float* pg   = (float*)p;
    cudaGetSymbolAddress(&p, g_sthat);    float* pst  = (float*)p;
    cudaGetSymbolAddress(&p, g_bias_e);   float* pbe  = (float*)p;
    cudaGetSymbolAddress(&p, g_bias_d);   float* pbd  = (float*)p;
    cudaGetSymbolAddress(&p, g_et_part);  float* pet  = (float*)p;
    cudaGetSymbolAddress(&p, g_etd_part); float* petd = (float*)p;
    cudaGetSymbolAddress(&p, g_ctd);      float* pctd = (float*)p;
    cudaGetSymbolAddress(&p, g_outfeat);  float* pof  = (float*)p;
    cudaGetSymbolAddress(&p, g_logits);   float* plg  = (float*)p;
    cudaGetSymbolAddress(&p, g_bbf);      __nv_bfloat16* pbb = (__nv_bfloat16*)p;
    cudaGetSymbolAddress(&p, g_wpbf);     __nv_bfloat16* pwp = (__nv_bfloat16*)p;
    cudaGetSymbolAddress(&p, g_v1bf);     __nv_bfloat16* pv1 = (__nv_bfloat16*)p;
    const float* nf = nullptr;

    cudaFuncSetAttribute((const void*)mma3<0, 1024, 400>, cudaFuncAttributeMaxDynamicSharedMemorySize, M3_SMEM);
    cudaFuncSetAttribute((const void*)mma3<0, 512, 49>,   cudaFuncAttributeMaxDynamicSharedMemorySize, M3_SMEM);
    cudaFuncSetAttribute((const void*)mma3<1, 512, 1>,    cudaFuncAttributeMaxDynamicSharedMemorySize, M3_SMEM);

    // Launch order arranged so mma3-enc is capture index 5 (ncu -s 5 -c 1).
    // 0. x = cat(x_t, ct_e) @ xw^T + xb
    sgemm2<<<dim3(4, 4), 256>>>(x_t, E_, ct_e, 2 * H_, nf, 0,
                                xw, 1280, nf, 0, xb, nf, px, 256, 256, 1280);
    // 1. gates
    sgemm2<<<dim3(32, 4), 256>>>(px, 256, dec_h, 512, nf, 0,
                                 wih, 256, whh, 512, bih, bhh, pg, 256, 2048, 768);
    // 2. LSTM
    lstm_kernel<<<B_ * H_ / 256, 256>>>(dec_c, o_h, o_c);
    // 3. bias_e = st_hat @ Ws^T + Ws_b
    sgemm2<<<dim3(16, 4), 256>>>(pst, 1024, nf, 0, nf, 0,
                                 Wsw, 1024, nf, 0, Wsb, nf, pbe, 256, 1024, 1024);
    // 4. Whw -> bf16
    conv_bf16<<<512, 256>>>(Whw, pbb);
    // 5. encoder attention scores  (profiled launch)
    mma3<0, 1024, 400><<<dim3(8, 800), 256, M3_SMEM>>>(enc_out, pbb, pbe, vw, pet, 1024);
    // 6-7. other weight converts
    conv_bf16<<<128, 256>>>(Wpw, pwp);
    conv_bf16<<<12500, 256>>>(V1w, pv1);
    // 8. temporal softmax
    et_finalize<<<B_, 512>>>(sum_temp, enc_mask, o_sum);
    // 9. ct_e_new
    ctx_enc<<<B_, 256>>>(enc_out, o_cte);
    // 10. bias_d
    sgemm2<<<dim3(8, 4), 256>>>(o_h, 512, nf, 0, nf, 0,
                                Wsdw, 512, nf, 0, Wsdb, nf, pbd, 256, 512, 512);
    // 11. decoder attention scores
    mma3<0, 512, 49><<<dim3(4, 98), 256, M3_SMEM>>>(prev_s, pwp, pbd, vdw, petd, 512);
    // 12. ct_d + prev_s_new
    dec_attn_finalize<<<B_, 256>>>(prev_s, o_h, o_prev);
    // 13. p_gen
    pgen_kernel<<<B_, 256>>>(o_cte, pgw, pgb);
    // 14. outfeat
    sgemm2<<<dim3(8, 4), 256>>>(o_h, 512, o_cte, 1024, pctd, 512,
                                Vw, 2048, nf, 0, Vb, nf, pof, 256, 512, 2048);
    // 15. logits
    mma3<1, 512, 1><<<dim3(391, 2), 256, M3_SMEM>>>(pof, pv1, V1b, nf, plg, V_);
    // 16-17. softmax + final dist
    vocab_stats<<<B_, 512>>>();
    final_dist_kernel<<<B_, 512>>>(ext_vocab, o_fd);
}

// round 14
// speedup vs baseline: 1.2415x; 1.2415x over previous
#include <cuda_runtime.h>
#include <cuda_bf16.h>
#include <math.h>
#include <stdint.h>

#define DINL __device__ __forceinline__
#define B_   256
#define N_   400
#define H_   512
#define E_   256
#define V_   50000
#define OOV_ 50
#define T_   49

// -------- device scratch (allocation-free) --------
__device__ float g_x[B_ * E_];
__device__ float g_gates[B_ * 4 * H_];
__device__ float g_sthat[B_ * 2 * H_];
__device__ float g_bias_e[B_ * 2 * H_];
__device__ float g_bias_d[B_ * H_];
__device__ float g_et_part[B_ * N_ * 8];
__device__ float g_at[B_ * N_];
__device__ float g_etd_part[B_ * T_ * 4];
__device__ float g_ctd[B_ * H_];
__device__ float g_pgen[B_];
__device__ float g_outfeat[B_ * H_];
__device__ float g_logits[(size_t)B_ * V_];
__device__ float g_rmax[B_];
__device__ float g_rsum[B_];
__device__ __nv_bfloat16 g_abf[(size_t)B_ * N_ * 1024];  // enc_out bf16
__device__ __nv_bfloat16 g_bbf[1024 * 1024];             // Whw bf16
__device__ __nv_bfloat16 g_wpbf[512 * 512];              // Wprev bf16
__device__ __nv_bfloat16 g_psbf[B_ * T_ * H_];           // prev_s bf16
__device__ __nv_bfloat16 g_ofbf[B_ * H_];                // outfeat bf16
__device__ __nv_bfloat16 g_v1bf[(size_t)V_ * H_];        // V1 bf16

DINL unsigned pack_bf16(float x, float y) {
    __nv_bfloat162 h = __floats2bfloat162_rn(x, y);
    return *reinterpret_cast<unsigned*>(&h);
}
DINL void mma16816(float* d, const unsigned* a, const unsigned* b, const float* c) {
    asm volatile(
        "mma.sync.aligned.m16n8k16.row.col.f32.bf16.bf16.f32 "
        "{%0,%1,%2,%3}, {%4,%5,%6,%7}, {%8,%9}, {%10,%11,%12,%13};\n"
        : "=f"(d[0]), "=f"(d[1]), "=f"(d[2]), "=f"(d[3])
        : "r"(a[0]), "r"(a[1]), "r"(a[2]), "r"(a[3]), "r"(b[0]), "r"(b[1]),
          "f"(c[0]), "f"(c[1]), "f"(c[2]), "f"(c[3]));
}
DINL float sigm(float v) { return 1.f / (1.f + expf(-v)); }
DINL uint32_t smem_u32(const void* p) {
    uint32_t a;
    asm("{ .reg .u64 t; cvta.to.shared.u64 t, %1; cvt.u32.u64 %0, t; }" : "=r"(a) : "l"(p));
    return a;
}
#define LDSM4(r0, r1, r2, r3, addr) \
    asm volatile("ldmatrix.sync.aligned.m8n8.x4.shared.b16 {%0,%1,%2,%3}, [%4];" \
        : "=r"(r0), "=r"(r1), "=r"(r2), "=r"(r3) : "r"(addr))
#define CPA16(dst, src) \
    asm volatile("cp.async.cg.shared.global [%0], [%1], 16;" :: "r"(dst), "l"(src))
#define CPA_COMMIT() asm volatile("cp.async.commit_group;" ::: "memory")
#define CPA_WAIT1()  asm volatile("cp.async.wait_group 1;" ::: "memory")

DINL float4 cat3_v4(const float* p0, int w0, const float* p1, int w1,
                    const float* p2, int w2, int row, int k) {
    if (k < w0) return *(const float4*)(p0 + (size_t)row * w0 + k);
    k -= w0;
    if (k < w1) return *(const float4*)(p1 + (size_t)row * w1 + k);
    return *(const float4*)(p2 + (size_t)row * w2 + (k - w1));
}
DINL float4 cat2w_v4(const float* p0, int w0, const float* p1, int w1, int row, int k) {
    if (k < w0) return *(const float4*)(p0 + (size_t)row * w0 + k);
    return *(const float4*)(p1 + (size_t)row * w1 + (k - w0));
}

// ===== exact fp32 GEMM (R10-validated) =====
__global__ __launch_bounds__(256)
void sgemm2(const float* a0, int aw0, const float* a1, int aw1,
            const float* a2, int aw2,
            const float* w0, int ww0, const float* w1, int ww1,
            const float* b0, const float* b1,
            float* __restrict__ C, int M, int Nc, int K) {
    __shared__ float As[32][68];
    __shared__ float Ws[32][68];
    const int tid = threadIdx.x;
    const int n0 = blockIdx.x * 64, m0 = blockIdx.y * 64;
    const int lm  = tid & 63;
    const int lk4 = (tid >> 6) * 4;
    const int tx = tid & 15, ty = tid >> 4;

    float4 ra[2], rw[2];
    ra[0] = cat3_v4(a0, aw0, a1, aw1, a2, aw2, m0 + lm, lk4);
    ra[1] = cat3_v4(a0, aw0, a1, aw1, a2, aw2, m0 + lm, lk4 + 16);
    rw[0] = cat2w_v4(w0, ww0, w1, ww1, n0 + lm, lk4);
    rw[1] = cat2w_v4(w0, ww0, w1, ww1, n0 + lm, lk4 + 16);

    float acc[4][4];
#pragma unroll
    for (int i = 0; i < 4; i++)
#pragma unroll
        for (int j = 0; j < 4; j++) acc[i][j] = 0.f;

    for (int k0 = 0; k0 < K; k0 += 32) {
#pragma unroll
        for (int h = 0; h < 2; h++) {
            int kb = lk4 + h * 16;
            As[kb + 0][lm] = ra[h].x; As[kb + 1][lm] = ra[h].y;
            As[kb + 2][lm] = ra[h].z; As[kb + 3][lm] = ra[h].w;
            Ws[kb + 0][lm] = rw[h].x; Ws[kb + 1][lm] = rw[h].y;
            Ws[kb + 2][lm] = rw[h].z; Ws[kb + 3][lm] = rw[h].w;
        }
        __syncthreads();
        if (k0 + 32 < K) {
            ra[0] = cat3_v4(a0, aw0, a1, aw1, a2, aw2, m0 + lm, k0 + 32 + lk4);
            ra[1] = cat3_v4(a0, aw0, a1, aw1, a2, aw2, m0 + lm, k0 + 32 + lk4 + 16);
            rw[0] = cat2w_v4(w0, ww0, w1, ww1, n0 + lm, k0 + 32 + lk4);
            rw[1] = cat2w_v4(w0, ww0, w1, ww1, n0 + lm, k0 + 32 + lk4 + 16);
        }
#pragma unroll
        for (int kk = 0; kk < 32; kk++) {
            float4 av = *(const float4*)&As[kk][ty * 4];
            float4 bv = *(const float4*)&Ws[kk][tx * 4];
            acc[0][0] += av.x * bv.x; acc[0][1] += av.x * bv.y;
            acc[0][2] += av.x * bv.z; acc[0][3] += av.x * bv.w;
            acc[1][0] += av.y * bv.x; acc[1][1] += av.y * bv.y;
            acc[1][2] += av.y * bv.z; acc[1][3] += av.y * bv.w;
            acc[2][0] += av.z * bv.x; acc[2][1] += av.z * bv.y;
            acc[2][2] += av.z * bv.z; acc[2][3] += av.z * bv.w;
            acc[3][0] += av.w * bv.x; acc[3][1] += av.w * bv.y;
            acc[3][2] += av.w * bv.z; acc[3][3] += av.w * bv.w;
        }
        __syncthreads();
    }
#pragma unroll
    for (int i = 0; i < 4; i++) {
        int row = m0 + ty * 4 + i;
#pragma unroll
        for (int j = 0; j < 4; j++) {
            int col = n0 + tx * 4 + j;
            C[(size_t)row * Nc + col] = acc[i][j] + b0[col] + (b1 ? b1[col] : 0.f);
        }
    }
}

// ===== fp32 -> bf16 pre-convert =====
__global__ void conv_bf16(const float* __restrict__ src, __nv_bfloat16* __restrict__ dst) {
    size_t i = ((size_t)blockIdx.x * 256 + threadIdx.x) * 8;
    float4 a = *(const float4*)(src + i), b = *(const float4*)(src + i + 4);
    uint4 o;
    o.x = pack_bf16(a.x, a.y); o.y = pack_bf16(a.z, a.w);
    o.z = pack_bf16(b.x, b.y); o.w = pack_bf16(b.z, b.w);
    *(uint4*)(dst + i) = o;
}

// ===== tensor GEMM v4: all-cp.async, 3-stage, 128x256 tile, 64x64/warp =====
// C = Ab[M,KDIM](bf16) @ Bb[Ncols,KDIM](bf16)^T
// MODE 0: out[m*gridDim.x+bx] = sum_col tanh(acc+bias[r/TOK][col])*v[col]
// MODE 1: out[m*Ncols+col] = acc + bias[col]  (col guarded)
// stage: A 128 rows x 64B, stride 80 (10240B) + B 256 rows x 64B, stride 80 (20480B)
#define M4_STAGE 30720
#define M4_SMEM  (3 * M4_STAGE)

template <int MODE, int KDIM, int TOK>
__global__ __launch_bounds__(256, 1)
void mma4(const __nv_bfloat16* __restrict__ Ab, const __nv_bfloat16* __restrict__ Bb,
          const float* __restrict__ bias, const float* __restrict__ vvec,
          float* __restrict__ out, int Ncols) {
    extern __shared__ char smem[];
    const uint32_t sbu = smem_u32(smem);
    const int tid = threadIdx.x, lane = tid & 31, warp = tid >> 5;
    const int wm = warp >> 2, wn = warp & 3;          // 2 x 4 warps -> 64x64 tiles
    const int n0 = blockIdx.x * 256;
    const long m0 = (long)blockIdx.y * 128;
    const int KT = KDIM / 32;

    float acc[4][8][4];
#pragma unroll
    for (int i = 0; i < 4; i++)
#pragma unroll
        for (int j = 0; j < 8; j++)
#pragma unroll
            for (int c = 0; c < 4; c++) acc[i][j][c] = 0.f;

    auto cpA = [&](int kt, int buf) {
        uint32_t base = sbu + buf * M4_STAGE;
#pragma unroll
        for (int i = 0; i < 2; i++) {
            int c = tid + 256 * i;
            int row = c >> 2, seg = c & 3;
            const __nv_bfloat16* src = Ab + (m0 + row) * (size_t)KDIM + kt * 32 + seg * 8;
            CPA16(base + row * 80 + seg * 16, src);
        }
    };
    auto cpB = [&](int kt, int buf) {
        uint32_t base = sbu + buf * M4_STAGE + 10240;
#pragma unroll
        for (int i = 0; i < 4; i++) {
            int c = tid + 256 * i;
            int row = c >> 2, seg = c & 3;
            int gr = n0 + row;
            if (MODE == 1 && gr >= Ncols) gr = 0;
            const __nv_bfloat16* src = Bb + (size_t)gr * KDIM + kt * 32 + seg * 8;
            CPA16(base + row * 80 + seg * 16, src);
        }
    };

    const uint32_t a_lds = sbu + (wm * 64 + (lane & 15)) * 80 + (lane >> 4) * 16;
    const uint32_t b_lds = sbu + 10240 + (wn * 64 + (lane & 15)) * 80 + (lane >> 4) * 16;

    auto compute = [&](int buf) {
        uint32_t ab = a_lds + buf * M4_STAGE, bb = b_lds + buf * M4_STAGE;
#pragma unroll
        for (int s = 0; s < 2; s++) {
            unsigned af[4][4], bfr[8][2];
#pragma unroll
            for (int mi = 0; mi < 4; mi++)
                LDSM4(af[mi][0], af[mi][1], af[mi][2], af[mi][3], ab + mi * 1280 + s * 32);
#pragma unroll
            for (int p = 0; p < 4; p++) {
                unsigned r0, r1, r2, r3;
                LDSM4(r0, r1, r2, r3, bb + p * 1280 + s * 32);
                bfr[2 * p][0] = r0; bfr[2 * p][1] = r2;
                bfr[2 * p + 1][0] = r1; bfr[2 * p + 1][1] = r3;
            }
#pragma unroll
            for (int mi = 0; mi < 4; mi++)
#pragma unroll
                for (int ni = 0; ni < 8; ni++)
                    mma16816(acc[mi][ni], af[mi], bfr[ni], acc[mi][ni]);
        }
    };

    // prologue: stages 0,1 (one commit group per stage)
    cpA(0, 0); cpB(0, 0); CPA_COMMIT();
    if (KT > 1) { cpA(1, 1); cpB(1, 1); }
    CPA_COMMIT();

    for (int kt = 0; kt < KT; kt++) {
        CPA_WAIT1();           // group kt complete (group kt+1 may pend)
        __syncthreads();       // all warps past compute(kt-1); stage data visible
        if (kt + 2 < KT) { cpA(kt + 2, (kt + 2) % 3); cpB(kt + 2, (kt + 2) % 3); }
        CPA_COMMIT();          // always commit: keeps group arithmetic exact at tail
        compute(kt % 3);
    }
    __syncthreads();

    if (MODE == 0) {
        float rs[4][2];
#pragma unroll
        for (int mi = 0; mi < 4; mi++) { rs[mi][0] = 0.f; rs[mi][1] = 0.f; }
#pragma unroll
        for (int mi = 0; mi < 4; mi++)
#pragma unroll
            for (int ni = 0; ni < 8; ni++)
#pragma unroll
                for (int c = 0; c < 4; c++) {
                    int col = wn * 64 + ni * 8 + (lane & 3) * 2 + (c & 1);
                    long r = m0 + wm * 64 + mi * 16 + (lane >> 2) + (c >> 1) * 8;
                    int bb2 = (int)(r / TOK);
                    float x = acc[mi][ni][c] + bias[(size_t)bb2 * Ncols + n0 + col];
                    x = fminf(fmaxf(x, -15.f), 15.f);
                    float e = __expf(2.f * x);
                    rs[mi][c >> 1] += __fdividef(e - 1.f, e + 1.f) * vvec[n0 + col];
                }
#pragma unroll
        for (int mi = 0; mi < 4; mi++)
#pragma unroll
            for (int h = 0; h < 2; h++) {
                rs[mi][h] += __shfl_xor_sync(0xffffffffu, rs[mi][h], 1);
                rs[mi][h] += __shfl_xor_sync(0xffffffffu, rs[mi][h], 2);
            }
        float* red = (float*)smem;
        if ((lane & 3) == 0) {
#pragma unroll
            for (int mi = 0; mi < 4; mi++)
#pragma unroll
                for (int h = 0; h < 2; h++) {
                    int rl = wm * 64 + mi * 16 + (lane >> 2) + h * 8;
                    red[rl * 4 + wn] = rs[mi][h];
                }
        }
        __syncthreads();
        if (tid < 128)
            out[(m0 + tid) * gridDim.x + blockIdx.x] =
                red[tid * 4] + red[tid * 4 + 1] + red[tid * 4 + 2] + red[tid * 4 + 3];
    } else {
#pragma unroll
        for (int mi = 0; mi < 4; mi++)
#pragma unroll
            for (int ni = 0; ni < 8; ni++)
#pragma unroll
                for (int c = 0; c < 4; c++) {
                    int gcol = n0 + wn * 64 + ni * 8 + (lane & 3) * 2 + (c & 1);
                    long r = m0 + wm * 64 + mi * 16 + (lane >> 2) + (c >> 1) * 8;
                    if (gcol < Ncols)
                        out[(size_t)r * Ncols + gcol] = acc[mi][ni][c] + bias[gcol];
                }
    }
}

// ===== elementwise / reductions =====
__global__ void lstm_kernel(const float* __restrict__ dec_c,
                            float* __restrict__ o_h, float* __restrict__ o_c) {
    int idx = blockIdx.x * 256 + threadIdx.x;
    int b = idx >> 9, h = idx & 511;
    const float* g = g_gates + (size_t)b * 2048;
    float c  = sigm(g[512 + h]) * dec_c[idx] + sigm(g[h]) * tanhf(g[1024 + h]);
    float hn = sigm(g[1536 + h]) * tanhf(c);
    o_h[idx] = hn; o_c[idx] = c;
    g_sthat[(size_t)b * 1024 + h] = hn;
    g_sthat[(size_t)b * 1024 + 512 + h] = c;
}

__global__ void et_finalize(const float* __restrict__ sumt, const float* __restrict__ mask,
                            float* __restrict__ o_sum) {
    int b = blockIdx.x, n = threadIdx.x;   // 512 thr
    __shared__ float sh[512];
    float atv = 0.f;
    if (n < N_) {
        const float* p = g_et_part + (size_t)(b * N_ + n) * 4;
        float e = expf(p[0] + p[1] + p[2] + p[3]);
        float st = sumt[b * N_ + n];
        o_sum[b * N_ + n] = st + e;
        atv = (e / st) * mask[b * N_ + n];
    }
    sh[n] = atv; __syncthreads();
    for (int st = 256; st > 0; st >>= 1) { if (n < st) sh[n] += sh[n + st]; __syncthreads(); }
    if (n < N_) g_at[b * N_ + n] = atv / sh[0];
}

__global__ void ctx_enc(const float* __restrict__ enc, float* __restrict__ o_cte) {
    int b = blockIdx.x, t = threadIdx.x;   // 256 thr
    __shared__ float a_s[N_];
    for (int i = t; i < N_; i += 256) a_s[i] = g_at[b * N_ + i];
    __syncthreads();
    float4 acc = make_float4(0, 0, 0, 0);
    const float4* base = (const float4*)(enc + (size_t)b * N_ * 1024) + t;
#pragma unroll 4
    for (int n = 0; n < N_; ++n) {
        float4 v = base[(size_t)n * 256]; float w = a_s[n];
        acc.x += w * v.x; acc.y += w * v.y; acc.z += w * v.z; acc.w += w * v.w;
    }
    ((float4*)(o_cte + (size_t)b * 1024))[t] = acc;
}

__global__ void dec_attn_finalize(const float* __restrict__ prev_s,
                                  const float* __restrict__ h_new,
                                  float* __restrict__ o_prev) {
    int b = blockIdx.x, tid = threadIdx.x;  // 256 thr
    __shared__ float atd[T_];
    __shared__ float tot;
    if (tid < T_) {
        const float* p = g_etd_part + (size_t)(b * T_ + tid) * 2;
        atd[tid] = expf(p[0] + p[1]);
    }
    __syncthreads();
    if (tid == 0) { float s = 0.f; for (int i = 0; i < T_; ++i) s += atd[i]; tot = s; }
    __syncthreads();
    float inv = 1.f / tot;
#pragma unroll
    for (int cg = 0; cg < 2; ++cg) {
        int col = tid + cg * 256;
        float acc = 0.f;
        for (int t2 = 0; t2 < T_; ++t2)
            acc += atd[t2] * prev_s[((size_t)b * T_ + t2) * H_ + col];
        g_ctd[(size_t)b * H_ + col] = acc * inv;
    }
    for (int i = tid; i < T_ * H_; i += 256)
        o_prev[(size_t)b * (T_ + 1) * H_ + i] = prev_s[(size_t)b * T_ * H_ + i];
    for (int i = tid; i < H_; i += 256)
        o_prev[(size_t)b * (T_ + 1) * H_ + T_ * H_ + i] = h_new[(size_t)b * H_ + i];
}

__global__ void pgen_kernel(const float* __restrict__ cte,
                            const float* __restrict__ w, const float* __restrict__ bias) {
    int b = blockIdx.x, tid = threadIdx.x;  // 256 thr, K=2816
    float s = 0.f;
    for (int k = tid; k < 2816; k += 256) {
        float a;
        if (k < 1024)      a = cte[(size_t)b * 1024 + k];
        else if (k < 1536) a = g_ctd[(size_t)b * 512 + (k - 1024)];
        else if (k < 2560) a = g_sthat[(size_t)b * 1024 + (k - 1536)];
        else               a = g_x[(size_t)b * 256 + (k - 2560)];
        s += a * w[k];
    }
    __shared__ float sh[256];
    sh[tid] = s; __syncthreads();
    for (int st = 128; st > 0; st >>= 1) { if (tid < st) sh[tid] += sh[tid + st]; __syncthreads(); }
    if (tid == 0) g_pgen[b] = sigm(sh[0] + bias[0]);
}

__global__ void vocab_stats() {
    int b = blockIdx.x, tid = threadIdx.x;  // 512 thr
    const float* row = g_logits + (size_t)b * V_;
    __shared__ float sh[512];
    float m = -1e30f;
    for (int v = tid; v < V_; v += 512) m = fmaxf(m, row[v]);
    sh[tid] = m; __syncthreads();
    for (int st = 256; st > 0; st >>= 1) { if (tid < st) sh[tid] = fmaxf(sh[tid], sh[tid + st]); __syncthreads(); }
    float mx = sh[0]; __syncthreads();
    float s = 0.f;
    for (int v = tid; v < V_; v += 512) s += expf(row[v] - mx);
    sh[tid] = s; __syncthreads();
    for (int st = 256; st > 0; st >>= 1) { if (tid < st) sh[tid] += sh[tid + st]; __syncthreads(); }
    if (tid == 0) { g_rmax[b] = mx; g_rsum[b] = sh[0]; }
}

__global__ void final_dist_kernel(const int* __restrict__ idx, float* __restrict__ out) {
    int b = blockIdx.x, tid = threadIdx.x;  // 512 thr
    float pg = g_pgen[b], scale = pg / g_rsum[b], mx = g_rmax[b];
    float* row = out + (size_t)b * (V_ + OOV_);
    const float* lrow = g_logits + (size_t)b * V_;
    for (int v = tid; v < V_ + OOV_; v += 512)
        row[v] = (v < V_) ? expf(lrow[v] - mx) * scale : 0.f;
    __shared__ int   sidx[N_];
    __shared__ float sval[N_];
    float am = 1.f - pg;
    for (int n = tid; n < N_; n += 512) {
        sidx[n] = idx[b * N_ + n];
        sval[n] = am * g_at[b * N_ + n];
    }
    __syncthreads();
    if (tid < N_) {
        int my = sidx[tid];
        bool leader = true;
        for (int i = 0; i < tid; ++i) if (sidx[i] == my) { leader = false; break; }
        if (leader) {
            float s = 0.f;
            for (int i = tid; i < N_; ++i) if (sidx[i] == my) s += sval[i];
            row[my] += s;
        }
    }
}

// ===== host launcher =====
extern "C" void kernel_launch(void* const* d_in, const int* in_sizes, int n_in,
                              void* d_out, int out_size) {
    (void)in_sizes; (void)n_in; (void)out_size;
    const float* x_t       = (const float*)d_in[0];
    const float* dec_h     = (const float*)d_in[1];
    const float* dec_c     = (const float*)d_in[2];
    const float* enc_out   = (const float*)d_in[3];
    const float* enc_mask  = (const float*)d_in[4];
    const float* ct_e      = (const float*)d_in[5];
    const int*   ext_vocab = (const int*)  d_in[7];
    const float* sum_temp  = (const float*)d_in[8];
    const float* prev_s    = (const float*)d_in[9];
    const float* xw   = (const float*)d_in[10];
    const float* xb   = (const float*)d_in[11];
    const float* wih  = (const float*)d_in[12];
    const float* whh  = (const float*)d_in[13];
    const float* bih  = (const float*)d_in[14];
    const float* bhh  = (const float*)d_in[15];
    const float* pgw  = (const float*)d_in[16];
    const float* pgb  = (const float*)d_in[17];
    const float* Vw   = (const float*)d_in[18];
    const float* Vb   = (const float*)d_in[19];
    const float* V1w  = (const float*)d_in[20];
    const float* V1b  = (const float*)d_in[21];
    const float* Whw  = (const float*)d_in[22];
    const float* Wsw  = (const float*)d_in[23];
    const float* Wsb  = (const float*)d_in[24];
    const float* vw   = (const float*)d_in[25];
    const float* Wpw  = (const float*)d_in[26];
    const float* Wsdw = (const float*)d_in[27];
    const float* Wsdb = (const float*)d_in[28];
    const float* vdw  = (const float*)d_in[29];

    float* out = (float*)d_out;
    float* o_fd   = out;
    float* o_h    = out + (size_t)B_ * (V_ + OOV_);
    float* o_c    = o_h  + B_ * H_;
    float* o_cte  = o_c  + B_ * H_;
    float* o_sum  = o_cte + B_ * 2 * H_;
    float* o_prev = o_sum + B_ * N_;

    void* p;
    cudaGetSymbolAddress(&p, g_x);        float* px   = (float*)p;
    cudaGetSymbolAddress(&p, g_gates);    float* pg   = (float*)p;
    cudaGetSymbolAddress(&p, g_sthat);    float* pst  = (float*)p;
    cudaGetSymbolAddress(&p, g_bias_e);   float* pbe  = (float*)p;
    cudaGetSymbolAddress(&p, g_bias_d);   float* pbd  = (float*)p;
    cudaGetSymbolAddress(&p, g_et_part);  float* pet  = (float*)p;
    cudaGetSymbolAddress(&p, g_etd_part); float* petd = (float*)p;
    cudaGetSymbolAddress(&p, g_ctd);      float* pctd = (float*)p;
    cudaGetSymbolAddress(&p, g_outfeat);  float* pof  = (float*)p;
    cudaGetSymbolAddress(&p, g_logits);   float* plg  = (float*)p;
    cudaGetSymbolAddress(&p, g_abf);      __nv_bfloat16* pab = (__nv_bfloat16*)p;
    cudaGetSymbolAddress(&p, g_bbf);      __nv_bfloat16* pbb = (__nv_bfloat16*)p;
    cudaGetSymbolAddress(&p, g_wpbf);     __nv_bfloat16* pwp = (__nv_bfloat16*)p;
    cudaGetSymbolAddress(&p, g_psbf);     __nv_bfloat16* pps = (__nv_bfloat16*)p;
    cudaGetSymbolAddress(&p, g_ofbf);     __nv_bfloat16* pob = (__nv_bfloat16*)p;
    cudaGetSymbolAddress(&p, g_v1bf);     __nv_bfloat16* pv1 = (__nv_bfloat16*)p;
    const float* nf = nullptr;

    cudaFuncSetAttribute((const void*)mma4<0, 1024, 400>, cudaFuncAttributeMaxDynamicSharedMemorySize, M4_SMEM);
    cudaFuncSetAttribute((const void*)mma4<0, 512, 49>,   cudaFuncAttributeMaxDynamicSharedMemorySize, M4_SMEM);
    cudaFuncSetAttribute((const void*)mma4<1, 512, 1>,    cudaFuncAttributeMaxDynamicSharedMemorySize, M4_SMEM);

    // 0-1. big bf16 pre-converts (A and B of encoder GEMM)
    conv_bf16<<<51200, 256>>>(enc_out, pab);
    conv_bf16<<<512, 256>>>(Whw, pbb);
    // 2. x = cat(x_t, ct_e) @ xw^T + xb
    sgemm2<<<dim3(4, 4), 256>>>(x_t, E_, ct_e, 2 * H_, nf, 0,
                                xw, 1280, nf, 0, xb, nf, px, 256, 256, 1280);
    // 3. gates
    sgemm2<<<dim3(32, 4), 256>>>(px, 256, dec_h, 512, nf, 0,
                                 wih, 256, whh, 512, bih, bhh, pg, 256, 2048, 768);
    // 4. LSTM
    lstm_kernel<<<B_ * H_ / 256, 256>>>(dec_c, o_h, o_c);
    // 5. bias_e = st_hat @ Ws^T + Ws_b
    sgemm2<<<dim3(16, 4), 256>>>(pst, 1024, nf, 0, nf, 0,
                                 Wsw, 1024, nf, 0, Wsb, nf, pbe, 256, 1024, 1024);
    // 6. encoder attention scores (all-cp.async 3-stage tensor GEMM)
    mma4<0, 1024, 400><<<dim3(4, 800), 256, M4_SMEM>>>(pab, pbb, pbe, vw, pet, 1024);
    // 7-9. smaller converts
    conv_bf16<<<128, 256>>>(Wpw, pwp);
    conv_bf16<<<3136, 256>>>(prev_s, pps);
    conv_bf16<<<12500, 256>>>(V1w, pv1);
    // 10. temporal softmax
    et_finalize<<<B_, 512>>>(sum_temp, enc_mask, o_sum);
    // 11. ct_e_new (fp32 enc_out — exact)
    ctx_enc<<<B_, 256>>>(enc_out, o_cte);
    // 12. bias_d
    sgemm2<<<dim3(8, 4), 256>>>(o_h, 512, nf, 0, nf, 0,
                                Wsdw, 512, nf, 0, Wsdb, nf, pbd, 256, 512, 512);
    // 13. decoder attention scores
    mma4<0, 512, 49><<<dim3(2, 98), 256, M4_SMEM>>>(pps, pwp, pbd, vdw, petd, 512);
    // 14. ct_d + prev_s_new
    dec_attn_finalize<<<B_, 256>>>(prev_s, o_h, o_prev);
    // 15. p_gen
    pgen_kernel<<<B_, 256>>>(o_cte, pgw, pgb);
    // 16. outfeat
    sgemm2<<<dim3(8, 4), 256>>>(o_h, 512, o_cte, 1024, pctd, 512,
                                Vw, 2048, nf, 0, Vb, nf, pof, 256, 512, 2048);
    // 17-18. outfeat -> bf16, logits
    conv_bf16<<<64, 256>>>(pof, pob);
    mma4<1, 512, 1><<<dim3(196, 2), 256, M4_SMEM>>>(pob, pv1, V1b, nf, plg, V_);
    // 19-20. softmax + final dist
    vocab_stats<<<B_, 512>>>();
    final_dist_kernel<<<B_, 512>>>(ext_vocab, o_fd);
}

// round 15
// speedup vs baseline: 1.3378x; 1.0775x over previous
#include <cuda_runtime.h>
#include <cuda_bf16.h>
#include <math.h>
#include <stdint.h>

#define DINL __device__ __forceinline__
#define B_   256
#define N_   400
#define H_   512
#define E_   256
#define V_   50000
#define OOV_ 50
#define T_   49

// -------- device scratch (allocation-free) --------
__device__ float g_x[B_ * E_];
__device__ float g_gates[B_ * 4 * H_];
__device__ float g_sthat[B_ * 2 * H_];
__device__ float g_bias_e[B_ * 2 * H_];
__device__ float g_bias_d[B_ * H_];
__device__ float g_et_part[B_ * N_ * 8];
__device__ float g_at[B_ * N_];
__device__ float g_etd_part[B_ * T_ * 4];
__device__ float g_ctd[B_ * H_];
__device__ float g_pgen[B_];
__device__ float g_outfeat[B_ * H_];
__device__ float g_logits[(size_t)B_ * V_];
__device__ float g_rmax[B_];
__device__ float g_rsum[B_];
__device__ __nv_bfloat16 g_abf[(size_t)B_ * N_ * 1024];  // enc_out bf16
__device__ __nv_bfloat16 g_bbf[1024 * 1024];             // Whw bf16
__device__ __nv_bfloat16 g_wpbf[512 * 512];              // Wprev bf16
__device__ __nv_bfloat16 g_psbf[B_ * T_ * H_];           // prev_s bf16
__device__ __nv_bfloat16 g_ofbf[B_ * H_];                // outfeat bf16
__device__ __nv_bfloat16 g_v1bf[(size_t)V_ * H_];        // V1 bf16

DINL unsigned pack_bf16(float x, float y) {
    __nv_bfloat162 h = __floats2bfloat162_rn(x, y);
    return *reinterpret_cast<unsigned*>(&h);
}
DINL void mma16816(float* d, const unsigned* a, const unsigned* b, const float* c) {
    asm volatile(
        "mma.sync.aligned.m16n8k16.row.col.f32.bf16.bf16.f32 "
        "{%0,%1,%2,%3}, {%4,%5,%6,%7}, {%8,%9}, {%10,%11,%12,%13};\n"
        : "=f"(d[0]), "=f"(d[1]), "=f"(d[2]), "=f"(d[3])
        : "r"(a[0]), "r"(a[1]), "r"(a[2]), "r"(a[3]), "r"(b[0]), "r"(b[1]),
          "f"(c[0]), "f"(c[1]), "f"(c[2]), "f"(c[3]));
}
DINL float sigm(float v) { return 1.f / (1.f + expf(-v)); }
DINL uint32_t smem_u32(const void* p) {
    uint32_t a;
    asm("{ .reg .u64 t; cvta.to.shared.u64 t, %1; cvt.u32.u64 %0, t; }" : "=r"(a) : "l"(p));
    return a;
}
#define LDSM4(r0, r1, r2, r3, addr) \
    asm volatile("ldmatrix.sync.aligned.m8n8.x4.shared.b16 {%0,%1,%2,%3}, [%4];" \
        : "=r"(r0), "=r"(r1), "=r"(r2), "=r"(r3) : "r"(addr))
#define CPA16(dst, src) \
    asm volatile("cp.async.cg.shared.global [%0], [%1], 16;" :: "r"(dst), "l"(src))
#define CPA_COMMIT() asm volatile("cp.async.commit_group;" ::: "memory")
#define CPA_WAIT1()  asm volatile("cp.async.wait_group 1;" ::: "memory")

DINL float4 cat3_v4(const float* p0, int w0, const float* p1, int w1,
                    const float* p2, int w2, int row, int k) {
    if (k < w0) return *(const float4*)(p0 + (size_t)row * w0 + k);
    k -= w0;
    if (k < w1) return *(const float4*)(p1 + (size_t)row * w1 + k);
    return *(const float4*)(p2 + (size_t)row * w2 + (k - w1));
}
DINL float4 cat2w_v4(const float* p0, int w0, const float* p1, int w1, int row, int k) {
    if (k < w0) return *(const float4*)(p0 + (size_t)row * w0 + k);
    return *(const float4*)(p1 + (size_t)row * w1 + (k - w0));
}

// ===== exact fp32 GEMM (R10-validated) =====
__global__ __launch_bounds__(256)
void sgemm2(const float* a0, int aw0, const float* a1, int aw1,
            const float* a2, int aw2,
            const float* w0, int ww0, const float* w1, int ww1,
            const float* b0, const float* b1,
            float* __restrict__ C, int M, int Nc, int K) {
    __shared__ float As[32][68];
    __shared__ float Ws[32][68];
    const int tid = threadIdx.x;
    const int n0 = blockIdx.x * 64, m0 = blockIdx.y * 64;
    const int lm  = tid & 63;
    const int lk4 = (tid >> 6) * 4;
    const int tx = tid & 15, ty = tid >> 4;

    float4 ra[2], rw[2];
    ra[0] = cat3_v4(a0, aw0, a1, aw1, a2, aw2, m0 + lm, lk4);
    ra[1] = cat3_v4(a0, aw0, a1, aw1, a2, aw2, m0 + lm, lk4 + 16);
    rw[0] = cat2w_v4(w0, ww0, w1, ww1, n0 + lm, lk4);
    rw[1] = cat2w_v4(w0, ww0, w1, ww1, n0 + lm, lk4 + 16);

    float acc[4][4];
#pragma unroll
    for (int i = 0; i < 4; i++)
#pragma unroll
        for (int j = 0; j < 4; j++) acc[i][j] = 0.f;

    for (int k0 = 0; k0 < K; k0 += 32) {
#pragma unroll
        for (int h = 0; h < 2; h++) {
            int kb = lk4 + h * 16;
            As[kb + 0][lm] = ra[h].x; As[kb + 1][lm] = ra[h].y;
            As[kb + 2][lm] = ra[h].z; As[kb + 3][lm] = ra[h].w;
            Ws[kb + 0][lm] = rw[h].x; Ws[kb + 1][lm] = rw[h].y;
            Ws[kb + 2][lm] = rw[h].z; Ws[kb + 3][lm] = rw[h].w;
        }
        __syncthreads();
        if (k0 + 32 < K) {
            ra[0] = cat3_v4(a0, aw0, a1, aw1, a2, aw2, m0 + lm, k0 + 32 + lk4);
            ra[1] = cat3_v4(a0, aw0, a1, aw1, a2, aw2, m0 + lm, k0 + 32 + lk4 + 16);
            rw[0] = cat2w_v4(w0, ww0, w1, ww1, n0 + lm, k0 + 32 + lk4);
            rw[1] = cat2w_v4(w0, ww0, w1, ww1, n0 + lm, k0 + 32 + lk4 + 16);
        }
#pragma unroll
        for (int kk = 0; kk < 32; kk++) {
            float4 av = *(const float4*)&As[kk][ty * 4];
            float4 bv = *(const float4*)&Ws[kk][tx * 4];
            acc[0][0] += av.x * bv.x; acc[0][1] += av.x * bv.y;
            acc[0][2] += av.x * bv.z; acc[0][3] += av.x * bv.w;
            acc[1][0] += av.y * bv.x; acc[1][1] += av.y * bv.y;
            acc[1][2] += av.y * bv.z; acc[1][3] += av.y * bv.w;
            acc[2][0] += av.z * bv.x; acc[2][1] += av.z * bv.y;
            acc[2][2] += av.z * bv.z; acc[2][3] += av.z * bv.w;
            acc[3][0] += av.w * bv.x; acc[3][1] += av.w * bv.y;
            acc[3][2] += av.w * bv.z; acc[3][3] += av.w * bv.w;
        }
        __syncthreads();
    }
#pragma unroll
    for (int i = 0; i < 4; i++) {
        int row = m0 + ty * 4 + i;
#pragma unroll
        for (int j = 0; j < 4; j++) {
            int col = n0 + tx * 4 + j;
            C[(size_t)row * Nc + col] = acc[i][j] + b0[col] + (b1 ? b1[col] : 0.f);
        }
    }
}

// ===== fp32 -> bf16 converts =====
__global__ void conv_bf16(const float* __restrict__ src, __nv_bfloat16* __restrict__ dst) {
    size_t i = ((size_t)blockIdx.x * 256 + threadIdx.x) * 8;
    float4 a = *(const float4*)(src + i), b = *(const float4*)(src + i + 4);
    uint4 o;
    o.x = pack_bf16(a.x, a.y); o.y = pack_bf16(a.z, a.w);
    o.z = pack_bf16(b.x, b.y); o.w = pack_bf16(b.z, b.w);
    *(uint4*)(dst + i) = o;
}
// dual convert: blocks [0, nblk0) -> src0/dst0, rest -> src1/dst1
__global__ void conv_dual(const float* __restrict__ s0, __nv_bfloat16* __restrict__ d0,
                          const float* __restrict__ s1, __nv_bfloat16* __restrict__ d1,
                          int nblk0) {
    const float* src; __nv_bfloat16* dst; size_t base;
    if ((int)blockIdx.x < nblk0) { src = s0; dst = d0; base = (size_t)blockIdx.x; }
    else { src = s1; dst = d1; base = (size_t)(blockIdx.x - nblk0); }
    size_t i = (base * 256 + threadIdx.x) * 8;
    float4 a = *(const float4*)(src + i), b = *(const float4*)(src + i + 4);
    uint4 o;
    o.x = pack_bf16(a.x, a.y); o.y = pack_bf16(a.z, a.w);
    o.z = pack_bf16(b.x, b.y); o.w = pack_bf16(b.z, b.w);
    *(uint4*)(dst + i) = o;
}

// ===== tensor GEMM v5: all-cp.async, 3-stage, KC=64, 128x256 tile, 64x64/warp =====
// C = Ab[M,KDIM](bf16) @ Bb[Ncols,KDIM](bf16)^T
// MODE 0: out[m*gridDim.x+bx] = sum_col tanh(acc+bias[r/TOK][col])*v[col]
// MODE 1: out[m*Ncols+col] = acc + bias[col]  (col guarded)
// stage: A 128 rows x 128B (stride 144 -> 18432B) + B 256 rows x 128B (36864B) = 55296B
#define M5_STAGE 55296
#define M5_SMEM  (3 * M5_STAGE)

template <int MODE, int KDIM, int TOK>
__global__ __launch_bounds__(256, 1)
void mma5(const __nv_bfloat16* __restrict__ Ab, const __nv_bfloat16* __restrict__ Bb,
          const float* __restrict__ bias, const float* __restrict__ vvec,
          float* __restrict__ out, int Ncols) {
    extern __shared__ char smem[];
    const uint32_t sbu = smem_u32(smem);
    const int tid = threadIdx.x, lane = tid & 31, warp = tid >> 5;
    const int wm = warp >> 2, wn = warp & 3;          // 2 x 4 warps -> 64x64 tiles
    const int n0 = blockIdx.x * 256;
    const long m0 = (long)blockIdx.y * 128;
    const int KT = KDIM / 64;

    float acc[4][8][4];
#pragma unroll
    for (int i = 0; i < 4; i++)
#pragma unroll
        for (int j = 0; j < 8; j++)
#pragma unroll
            for (int c = 0; c < 4; c++) acc[i][j][c] = 0.f;

    auto cpA = [&](int kt, int buf) {
        uint32_t base = sbu + buf * M5_STAGE;
#pragma unroll
        for (int i = 0; i < 4; i++) {
            int seg = tid + 256 * i;                 // 1024 segs: 128 rows x 8
            int row = seg >> 3, c = seg & 7;
            const __nv_bfloat16* src = Ab + (m0 + row) * (size_t)KDIM + kt * 64 + c * 8;
            CPA16(base + row * 144 + c * 16, src);
        }
    };
    auto cpB = [&](int kt, int buf) {
        uint32_t base = sbu + buf * M5_STAGE + 18432;
#pragma unroll
        for (int i = 0; i < 8; i++) {
            int seg = tid + 256 * i;                 // 2048 segs: 256 rows x 8
            int row = seg >> 3, c = seg & 7;
            int gr = n0 + row;
            if (MODE == 1 && gr >= Ncols) gr = 0;
            const __nv_bfloat16* src = Bb + (size_t)gr * KDIM + kt * 64 + c * 8;
            CPA16(base + row * 144 + c * 16, src);
        }
    };

    const uint32_t a_lds = sbu + (wm * 64 + (lane & 15)) * 144 + (lane >> 4) * 16;
    const uint32_t b_lds = sbu + 18432 + (wn * 64 + (lane & 15)) * 144 + (lane >> 4) * 16;

    auto compute = [&](int buf) {
        uint32_t ab = a_lds + buf * M5_STAGE, bb = b_lds + buf * M5_STAGE;
#pragma unroll
        for (int s = 0; s < 4; s++) {                // 4 k-slices of 16
            unsigned af[4][4], bfr[8][2];
#pragma unroll
            for (int mi = 0; mi < 4; mi++)
                LDSM4(af[mi][0], af[mi][1], af[mi][2], af[mi][3], ab + mi * 2304 + s * 32);
#pragma unroll
            for (int p = 0; p < 4; p++) {
                unsigned r0, r1, r2, r3;
                LDSM4(r0, r1, r2, r3, bb + p * 2304 + s * 32);
                bfr[2 * p][0] = r0; bfr[2 * p][1] = r2;
                bfr[2 * p + 1][0] = r1; bfr[2 * p + 1][1] = r3;
            }
#pragma unroll
            for (int mi = 0; mi < 4; mi++)
#pragma unroll
                for (int ni = 0; ni < 8; ni++)
                    mma16816(acc[mi][ni], af[mi], bfr[ni], acc[mi][ni]);
        }
    };

    // prologue: stages 0,1
    cpA(0, 0); cpB(0, 0); CPA_COMMIT();
    if (KT > 1) { cpA(1, 1); cpB(1, 1); }
    CPA_COMMIT();

    for (int kt = 0; kt < KT; kt++) {
        CPA_WAIT1();
        __syncthreads();
        if (kt + 2 < KT) { cpA(kt + 2, (kt + 2) % 3); cpB(kt + 2, (kt + 2) % 3); }
        CPA_COMMIT();
        compute(kt % 3);
    }
    __syncthreads();

    if (MODE == 0) {
        float rs[4][2];
#pragma unroll
        for (int mi = 0; mi < 4; mi++) { rs[mi][0] = 0.f; rs[mi][1] = 0.f; }
#pragma unroll
        for (int mi = 0; mi < 4; mi++)
#pragma unroll
            for (int ni = 0; ni < 8; ni++)
#pragma unroll
                for (int c = 0; c < 4; c++) {
                    int col = wn * 64 + ni * 8 + (lane & 3) * 2 + (c & 1);
                    long r = m0 + wm * 64 + mi * 16 + (lane >> 2) + (c >> 1) * 8;
                    int bb2 = (int)(r / TOK);
                    float x = acc[mi][ni][c] + bias[(size_t)bb2 * Ncols + n0 + col];
                    x = fminf(fmaxf(x, -15.f), 15.f);
                    float e = __expf(2.f * x);
                    rs[mi][c >> 1] += __fdividef(e - 1.f, e + 1.f) * vvec[n0 + col];
                }
#pragma unroll
        for (int mi = 0; mi < 4; mi++)
#pragma unroll
            for (int h = 0; h < 2; h++) {
                rs[mi][h] += __shfl_xor_sync(0xffffffffu, rs[mi][h], 1);
                rs[mi][h] += __shfl_xor_sync(0xffffffffu, rs[mi][h], 2);
            }
        float* red = (float*)smem;
        if ((lane & 3) == 0) {
#pragma unroll
            for (int mi = 0; mi < 4; mi++)
#pragma unroll
                for (int h = 0; h < 2; h++) {
                    int rl = wm * 64 + mi * 16 + (lane >> 2) + h * 8;
                    red[rl * 4 + wn] = rs[mi][h];
                }
        }
        __syncthreads();
        if (tid < 128)
            out[(m0 + tid) * gridDim.x + blockIdx.x] =
                red[tid * 4] + red[tid * 4 + 1] + red[tid * 4 + 2] + red[tid * 4 + 3];
    } else {
#pragma unroll
        for (int mi = 0; mi < 4; mi++)
#pragma unroll
            for (int ni = 0; ni < 8; ni++)
#pragma unroll
                for (int c = 0; c < 4; c++) {
                    int gcol = n0 + wn * 64 + ni * 8 + (lane & 3) * 2 + (c & 1);
                    long r = m0 + wm * 64 + mi * 16 + (lane >> 2) + (c >> 1) * 8;
                    if (gcol < Ncols)
                        out[(size_t)r * Ncols + gcol] = acc[mi][ni][c] + bias[gcol];
                }
    }
}

// ===== elementwise / reductions =====
__global__ void lstm_kernel(const float* __restrict__ dec_c,
                            float* __restrict__ o_h, float* __restrict__ o_c) {
    int idx = blockIdx.x * 256 + threadIdx.x;
    int b = idx >> 9, h = idx & 511;
    const float* g = g_gates + (size_t)b * 2048;
    float c  = sigm(g[512 + h]) * dec_c[idx] + sigm(g[h]) * tanhf(g[1024 + h]);
    float hn = sigm(g[1536 + h]) * tanhf(c);
    o_h[idx] = hn; o_c[idx] = c;
    g_sthat[(size_t)b * 1024 + h] = hn;
    g_sthat[(size_t)b * 1024 + 512 + h] = c;
}

__global__ void et_finalize(const float* __restrict__ sumt, const float* __restrict__ mask,
                            float* __restrict__ o_sum) {
    int b = blockIdx.x, n = threadIdx.x;   // 512 thr
    __shared__ float sh[512];
    float atv = 0.f;
    if (n < N_) {
        const float* p = g_et_part + (size_t)(b * N_ + n) * 4;
        float e = expf(p[0] + p[1] + p[2] + p[3]);
        float st = sumt[b * N_ + n];
        o_sum[b * N_ + n] = st + e;
        atv = (e / st) * mask[b * N_ + n];
    }
    sh[n] = atv; __syncthreads();
    for (int st = 256; st > 0; st >>= 1) { if (n < st) sh[n] += sh[n + st]; __syncthreads(); }
    if (n < N_) g_at[b * N_ + n] = atv / sh[0];
}

__global__ void ctx_enc(const float* __restrict__ enc, float* __restrict__ o_cte) {
    int b = blockIdx.x, t = threadIdx.x;   // 256 thr
    __shared__ float a_s[N_];
    for (int i = t; i < N_; i += 256) a_s[i] = g_at[b * N_ + i];
    __syncthreads();
    float4 acc = make_float4(0, 0, 0, 0);
    const float4* base = (const float4*)(enc + (size_t)b * N_ * 1024) + t;
#pragma unroll 4
    for (int n = 0; n < N_; ++n) {
        float4 v = base[(size_t)n * 256]; float w = a_s[n];
        acc.x += w * v.x; acc.y += w * v.y; acc.z += w * v.z; acc.w += w * v.w;
    }
    ((float4*)(o_cte + (size_t)b * 1024))[t] = acc;
}

__global__ void dec_attn_finalize(const float* __restrict__ prev_s,
                                  const float* __restrict__ h_new,
                                  float* __restrict__ o_prev) {
    int b = blockIdx.x, tid = threadIdx.x;  // 256 thr
    __shared__ float atd[T_];
    __shared__ float tot;
    if (tid < T_) {
        const float* p = g_etd_part + (size_t)(b * T_ + tid) * 2;
        atd[tid] = expf(p[0] + p[1]);
    }
    __syncthreads();
    if (tid == 0) { float s = 0.f; for (int i = 0; i < T_; ++i) s += atd[i]; tot = s; }
    __syncthreads();
    float inv = 1.f / tot;
#pragma unroll
    for (int cg = 0; cg < 2; ++cg) {
        int col = tid + cg * 256;
        float acc = 0.f;
        for (int t2 = 0; t2 < T_; ++t2)
            acc += atd[t2] * prev_s[((size_t)b * T_ + t2) * H_ + col];
        g_ctd[(size_t)b * H_ + col] = acc * inv;
    }
    for (int i = tid; i < T_ * H_; i += 256)
        o_prev[(size_t)b * (T_ + 1) * H_ + i] = prev_s[(size_t)b * T_ * H_ + i];
    for (int i = tid; i < H_; i += 256)
        o_prev[(size_t)b * (T_ + 1) * H_ + T_ * H_ + i] = h_new[(size_t)b * H_ + i];
}

__global__ void pgen_kernel(const float* __restrict__ cte,
                            const float* __restrict__ w, const float* __restrict__ bias) {
    int b = blockIdx.x, tid = threadIdx.x;  // 256 thr, K=2816
    float s = 0.f;
    for (int k = tid; k < 2816; k += 256) {
        float a;
        if (k < 1024)      a = cte[(size_t)b * 1024 + k];
        else if (k < 1536) a = g_ctd[(size_t)b * 512 + (k - 1024)];
        else if (k < 2560) a = g_sthat[(size_t)b * 1024 + (k - 1536)];
        else               a = g_x[(size_t)b * 256 + (k - 2560)];
        s += a * w[k];
    }
    __shared__ float sh[256];
    sh[tid] = s; __syncthreads();
    for (int st = 128; st > 0; st >>= 1) { if (tid < st) sh[tid] += sh[tid + st]; __syncthreads(); }
    if (tid == 0) g_pgen[b] = sigm(sh[0] + bias[0]);
}

__global__ void vocab_stats() {
    int b = blockIdx.x, tid = threadIdx.x;  // 512 thr
    const float* row = g_logits + (size_t)b * V_;
    __shared__ float sh[512];
    float m = -1e30f;
    for (int v = tid; v < V_; v += 512) m = fmaxf(m, row[v]);
    sh[tid] = m; __syncthreads();
    for (int st = 256; st > 0; st >>= 1) { if (tid < st) sh[tid] = fmaxf(sh[tid], sh[tid + st]); __syncthreads(); }
    float mx = sh[0]; __syncthreads();
    float s = 0.f;
    for (int v = tid; v < V_; v += 512) s += expf(row[v] - mx);
    sh[tid] = s; __syncthreads();
    for (int st = 256; st > 0; st >>= 1) { if (tid < st) sh[tid] += sh[tid + st]; __syncthreads(); }
    if (tid == 0) { g_rmax[b] = mx; g_rsum[b] = sh[0]; }
}

__global__ void final_dist_kernel(const int* __restrict__ idx, float* __restrict__ out) {
    int b = blockIdx.x, tid = threadIdx.x;  // 512 thr
    float pg = g_pgen[b], scale = pg / g_rsum[b], mx = g_rmax[b];
    float* row = out + (size_t)b * (V_ + OOV_);
    const float* lrow = g_logits + (size_t)b * V_;
    for (int v = tid; v < V_ + OOV_; v += 512)
        row[v] = (v < V_) ? expf(lrow[v] - mx) * scale : 0.f;
    __shared__ int   sidx[N_];
    __shared__ float sval[N_];
    float am = 1.f - pg;
    for (int n = tid; n < N_; n += 512) {
        sidx[n] = idx[b * N_ + n];
        sval[n] = am * g_at[b * N_ + n];
    }
    __syncthreads();
    if (tid < N_) {
        int my = sidx[tid];
        bool leader = true;
        for (int i = 0; i < tid; ++i) if (sidx[i] == my) { leader = false; break; }
        if (leader) {
            float s = 0.f;
            for (int i = tid; i < N_; ++i) if (sidx[i] == my) s += sval[i];
            row[my] += s;
        }
    }
}

// ===== host launcher =====
extern "C" void kernel_launch(void* const* d_in, const int* in_sizes, int n_in,
                              void* d_out, int out_size) {
    (void)in_sizes; (void)n_in; (void)out_size;
    const float* x_t       = (const float*)d_in[0];
    const float* dec_h     = (const float*)d_in[1];
    const float* dec_c     = (const float*)d_in[2];
    const float* enc_out   = (const float*)d_in[3];
    const float* enc_mask  = (const float*)d_in[4];
    const float* ct_e      = (const float*)d_in[5];
    const int*   ext_vocab = (const int*)  d_in[7];
    const float* sum_temp  = (const float*)d_in[8];
    const float* prev_s    = (const float*)d_in[9];
    const float* xw   = (const float*)d_in[10];
    const float* xb   = (const float*)d_in[11];
    const float* wih  = (const float*)d_in[12];
    const float* whh  = (const float*)d_in[13];
    const float* bih  = (const float*)d_in[14];
    const float* bhh  = (const float*)d_in[15];
    const float* pgw  = (const float*)d_in[16];
    const float* pgb  = (const float*)d_in[17];
    const float* Vw   = (const float*)d_in[18];
    const float* Vb   = (const float*)d_in[19];
    const float* V1w  = (const float*)d_in[20];
    const float* V1b  = (const float*)d_in[21];
    const float* Whw  = (const float*)d_in[22];
    const float* Wsw  = (const float*)d_in[23];
    const float* Wsb  = (const float*)d_in[24];
    const float* vw   = (const float*)d_in[25];
    const float* Wpw  = (const float*)d_in[26];
    const float* Wsdw = (const float*)d_in[27];
    const float* Wsdb = (const float*)d_in[28];
    const float* vdw  = (const float*)d_in[29];

    float* out = (float*)d_out;
    float* o_fd   = out;
    float* o_h    = out + (size_t)B_ * (V_ + OOV_);
    float* o_c    = o_h  + B_ * H_;
    float* o_cte  = o_c  + B_ * H_;
    float* o_sum  = o_cte + B_ * 2 * H_;
    float* o_prev = o_sum + B_ * N_;

    void* p;
    cudaGetSymbolAddress(&p, g_x);        float* px   = (float*)p;
    cudaGetSymbolAddress(&p, g_gates);    float* pg   = (float*)p;
    cudaGetSymbolAddress(&p, g_sthat);    float* pst  = (float*)p;
    cudaGetSymbolAddress(&p, g_bias_e);   float* pbe  = (float*)p;
    cudaGetSymbolAddress(&p, g_bias_d);   float* pbd  = (float*)p;
    cudaGetSymbolAddress(&p, g_et_part);  float* pet  = (float*)p;
    cudaGetSymbolAddress(&p, g_etd_part); float* petd = (float*)p;
    cudaGetSymbolAddress(&p, g_ctd);      float* pctd = (float*)p;
    cudaGetSymbolAddress(&p, g_outfeat);  float* pof  = (float*)p;
    cudaGetSymbolAddress(&p, g_logits);   float* plg  = (float*)p;
    cudaGetSymbolAddress(&p, g_abf);      __nv_bfloat16* pab = (__nv_bfloat16*)p;
    cudaGetSymbolAddress(&p, g_bbf);      __nv_bfloat16* pbb = (__nv_bfloat16*)p;
    cudaGetSymbolAddress(&p, g_wpbf);     __nv_bfloat16* pwp = (__nv_bfloat16*)p;
    cudaGetSymbolAddress(&p, g_psbf);     __nv_bfloat16* pps = (__nv_bfloat16*)p;
    cudaGetSymbolAddress(&p, g_ofbf);     __nv_bfloat16* pob = (__nv_bfloat16*)p;
    cudaGetSymbolAddress(&p, g_v1bf);     __nv_bfloat16* pv1 = (__nv_bfloat16*)p;
    const float* nf = nullptr;

    cudaFuncSetAttribute((const void*)mma5<0, 1024, 400>, cudaFuncAttributeMaxDynamicSharedMemorySize, M5_SMEM);
    cudaFuncSetAttribute((const void*)mma5<0, 512, 49>,   cudaFuncAttributeMaxDynamicSharedMemorySize, M5_SMEM);
    cudaFuncSetAttribute((const void*)mma5<1, 512, 1>,    cudaFuncAttributeMaxDynamicSharedMemorySize, M5_SMEM);

    // Order: mma5-enc is capture index 5 for ncu (-s 5 -c 1).
    // 0. x = cat(x_t, ct_e) @ xw^T + xb
    sgemm2<<<dim3(4, 4), 256>>>(x_t, E_, ct_e, 2 * H_, nf, 0,
                                xw, 1280, nf, 0, xb, nf, px, 256, 256, 1280);
    // 1. gates
    sgemm2<<<dim3(32, 4), 256>>>(px, 256, dec_h, 512, nf, 0,
                                 wih, 256, whh, 512, bih, bhh, pg, 256, 2048, 768);
    // 2. LSTM
    lstm_kernel<<<B_ * H_ / 256, 256>>>(dec_c, o_h, o_c);
    // 3. bias_e = st_hat @ Ws^T + Ws_b
    sgemm2<<<dim3(16, 4), 256>>>(pst, 1024, nf, 0, nf, 0,
                                 Wsw, 1024, nf, 0, Wsb, nf, pbe, 256, 1024, 1024);
    // 4. enc_out + Whw -> bf16 in one kernel
    conv_dual<<<51712, 256>>>(enc_out, pab, Whw, pbb, 51200);
    // 5. encoder attention scores  (profiled launch)
    mma5<0, 1024, 400><<<dim3(4, 800), 256, M5_SMEM>>>(pab, pbb, pbe, vw, pet, 1024);
    // 6-8. smaller converts
    conv_bf16<<<128, 256>>>(Wpw, pwp);
    conv_bf16<<<3136, 256>>>(prev_s, pps);
    conv_bf16<<<12500, 256>>>(V1w, pv1);
    // 9. temporal softmax
    et_finalize<<<B_, 512>>>(sum_temp, enc_mask, o_sum);
    // 10. ct_e_new (fp32 enc_out — exact)
    ctx_enc<<<B_, 256>>>(enc_out, o_cte);
    // 11. bias_d
    sgemm2<<<dim3(8, 4), 256>>>(o_h, 512, nf, 0, nf, 0,
                                Wsdw, 512, nf, 0, Wsdb, nf, pbd, 256, 512, 512);
    // 12. decoder attention scores
    mma5<0, 512, 49><<<dim3(2, 98), 256, M5_SMEM>>>(pps, pwp, pbd, vdw, petd, 512);
    // 13. ct_d + prev_s_new
    dec_attn_finalize<<<B_, 256>>>(prev_s, o_h, o_prev);
    // 14. p_gen
    pgen_kernel<<<B_, 256>>>(o_cte, pgw, pgb);
    // 15. outfeat
    sgemm2<<<dim3(8, 4), 256>>>(o_h, 512, o_cte, 1024, pctd, 512,
                                Vw, 2048, nf, 0, Vb, nf, pof, 256, 512, 2048);
    // 16-17. outfeat -> bf16, logits
    conv_bf16<<<64, 256>>>(pof, pob);
    mma5<1, 512, 1><<<dim3(196, 2), 256, M5_SMEM>>>(pob, pv1, V1b, nf, plg, V_);
    // 18-19. softmax + final dist
    vocab_stats<<<B_, 512>>>();
    final_dist_kernel<<<B_, 512>>>(ext_vocab, o_fd);
}

// round 16
// speedup vs baseline: 1.5080x; 1.1272x over previous
#include <cuda_runtime.h>
#include <cuda_bf16.h>
#include <math.h>
#include <stdint.h>

#define DINL __device__ __forceinline__
#define B_   256
#define N_   400
#define H_   512
#define E_   256
#define V_   50000
#define OOV_ 50
#define T_   49

// -------- device scratch (allocation-free) --------
__device__ float g_x[B_ * E_];
__device__ float g_gates[B_ * 4 * H_];
__device__ float g_sthat[B_ * 2 * H_];
__device__ float g_bias_e[B_ * 2 * H_];
__device__ float g_bias_d[B_ * H_];
__device__ float g_et_part[B_ * N_ * 8];
__device__ float g_at[B_ * N_];
__device__ float g_etd_part[B_ * T_ * 4];
__device__ float g_ctd[B_ * H_];
__device__ float g_pgen[B_];
__device__ float g_outfeat[B_ * H_];
__device__ float g_logits[(size_t)B_ * V_];
__device__ float g_rmax[B_];
__device__ float g_rsum[B_];
__device__ float g_part[4 * B_ * 4 * H_];                // split-K partials (max: gates)
__device__ __nv_bfloat16 g_abf[(size_t)B_ * N_ * 1024];  // enc_out bf16
__device__ __nv_bfloat16 g_bbf[1024 * 1024];             // Whw bf16
__device__ __nv_bfloat16 g_wpbf[512 * 512];              // Wprev bf16
__device__ __nv_bfloat16 g_psbf[B_ * T_ * H_];           // prev_s bf16
__device__ __nv_bfloat16 g_ofbf[B_ * H_];                // outfeat bf16
__device__ __nv_bfloat16 g_v1bf[(size_t)V_ * H_];        // V1 bf16

DINL unsigned pack_bf16(float x, float y) {
    __nv_bfloat162 h = __floats2bfloat162_rn(x, y);
    return *reinterpret_cast<unsigned*>(&h);
}
DINL void mma16816(float* d, const unsigned* a, const unsigned* b, const float* c) {
    asm volatile(
        "mma.sync.aligned.m16n8k16.row.col.f32.bf16.bf16.f32 "
        "{%0,%1,%2,%3}, {%4,%5,%6,%7}, {%8,%9}, {%10,%11,%12,%13};\n"
        : "=f"(d[0]), "=f"(d[1]), "=f"(d[2]), "=f"(d[3])
        : "r"(a[0]), "r"(a[1]), "r"(a[2]), "r"(a[3]), "r"(b[0]), "r"(b[1]),
          "f"(c[0]), "f"(c[1]), "f"(c[2]), "f"(c[3]));
}
DINL float sigm(float v) { return 1.f / (1.f + expf(-v)); }
DINL uint32_t smem_u32(const void* p) {
    uint32_t a;
    asm("{ .reg .u64 t; cvta.to.shared.u64 t, %1; cvt.u32.u64 %0, t; }" : "=r"(a) : "l"(p));
    return a;
}
#define LDSM4(r0, r1, r2, r3, addr) \
    asm volatile("ldmatrix.sync.aligned.m8n8.x4.shared.b16 {%0,%1,%2,%3}, [%4];" \
        : "=r"(r0), "=r"(r1), "=r"(r2), "=r"(r3) : "r"(addr))
#define CPA16(dst, src) \
    asm volatile("cp.async.cg.shared.global [%0], [%1], 16;" :: "r"(dst), "l"(src))
#define CPA_COMMIT() asm volatile("cp.async.commit_group;" ::: "memory")
#define CPA_WAIT1()  asm volatile("cp.async.wait_group 1;" ::: "memory")

DINL float4 cat3_v4(const float* p0, int w0, const float* p1, int w1,
                    const float* p2, int w2, int row, int k) {
    if (k < w0) return *(const float4*)(p0 + (size_t)row * w0 + k);
    k -= w0;
    if (k < w1) return *(const float4*)(p1 + (size_t)row * w1 + k);
    return *(const float4*)(p2 + (size_t)row * w2 + (k - w1));
}
DINL float4 cat2w_v4(const float* p0, int w0, const float* p1, int w1, int row, int k) {
    if (k < w0) return *(const float4*)(p0 + (size_t)row * w0 + k);
    return *(const float4*)(p1 + (size_t)row * w1 + (k - w0));
}

// ===== fp32 GEMM, split-K over blockIdx.z: part[z] = catA@catW^T over K-chunk z =====
__global__ __launch_bounds__(256)
void sgemm3(const float* a0, int aw0, const float* a1, int aw1,
            const float* a2, int aw2,
            const float* w0, int ww0, const float* w1, int ww1,
            float* __restrict__ part, int M, int Nc, int KS) {
    __shared__ float As[32][68];
    __shared__ float Ws[32][68];
    const int tid = threadIdx.x;
    const int n0 = blockIdx.x * 64, m0 = blockIdx.y * 64;
    const int kof = blockIdx.z * KS;
    const int lm  = tid & 63;
    const int lk4 = (tid >> 6) * 4;
    const int tx = tid & 15, ty = tid >> 4;

    float4 ra[2], rw[2];
    ra[0] = cat3_v4(a0, aw0, a1, aw1, a2, aw2, m0 + lm, kof + lk4);
    ra[1] = cat3_v4(a0, aw0, a1, aw1, a2, aw2, m0 + lm, kof + lk4 + 16);
    rw[0] = cat2w_v4(w0, ww0, w1, ww1, n0 + lm, kof + lk4);
    rw[1] = cat2w_v4(w0, ww0, w1, ww1, n0 + lm, kof + lk4 + 16);

    float acc[4][4];
#pragma unroll
    for (int i = 0; i < 4; i++)
#pragma unroll
        for (int j = 0; j < 4; j++) acc[i][j] = 0.f;

    for (int k0 = 0; k0 < KS; k0 += 32) {
#pragma unroll
        for (int h = 0; h < 2; h++) {
            int kb = lk4 + h * 16;
            As[kb + 0][lm] = ra[h].x; As[kb + 1][lm] = ra[h].y;
            As[kb + 2][lm] = ra[h].z; As[kb + 3][lm] = ra[h].w;
            Ws[kb + 0][lm] = rw[h].x; Ws[kb + 1][lm] = rw[h].y;
            Ws[kb + 2][lm] = rw[h].z; Ws[kb + 3][lm] = rw[h].w;
        }
        __syncthreads();
        if (k0 + 32 < KS) {
            int kn = kof + k0 + 32;
            ra[0] = cat3_v4(a0, aw0, a1, aw1, a2, aw2, m0 + lm, kn + lk4);
            ra[1] = cat3_v4(a0, aw0, a1, aw1, a2, aw2, m0 + lm, kn + lk4 + 16);
            rw[0] = cat2w_v4(w0, ww0, w1, ww1, n0 + lm, kn + lk4);
            rw[1] = cat2w_v4(w0, ww0, w1, ww1, n0 + lm, kn + lk4 + 16);
        }
#pragma unroll
        for (int kk = 0; kk < 32; kk++) {
            float4 av = *(const float4*)&As[kk][ty * 4];
            float4 bv = *(const float4*)&Ws[kk][tx * 4];
            acc[0][0] += av.x * bv.x; acc[0][1] += av.x * bv.y;
            acc[0][2] += av.x * bv.z; acc[0][3] += av.x * bv.w;
            acc[1][0] += av.y * bv.x; acc[1][1] += av.y * bv.y;
            acc[1][2] += av.y * bv.z; acc[1][3] += av.y * bv.w;
            acc[2][0] += av.z * bv.x; acc[2][1] += av.z * bv.y;
            acc[2][2] += av.z * bv.z; acc[2][3] += av.z * bv.w;
            acc[3][0] += av.w * bv.x; acc[3][1] += av.w * bv.y;
            acc[3][2] += av.w * bv.z; acc[3][3] += av.w * bv.w;
        }
        __syncthreads();
    }
    float* dst = part + (size_t)blockIdx.z * M * Nc;
#pragma unroll
    for (int i = 0; i < 4; i++) {
        int row = m0 + ty * 4 + i;
#pragma unroll
        for (int j = 0; j < 4; j++) {
            int col = n0 + tx * 4 + j;
            dst[(size_t)row * Nc + col] = acc[i][j];
        }
    }
}

// C[i] = part0+part1+part2+part3 (fixed order) + b0[col] (+ b1[col])
__global__ void reduce4(const float* __restrict__ part, const float* __restrict__ b0,
                        const float* __restrict__ b1, float* __restrict__ C,
                        int Nc, int total) {
    int i = (blockIdx.x * 256 + threadIdx.x) * 4;
    float4 s0 = *(const float4*)(part + i);
    float4 s1 = *(const float4*)(part + (size_t)total + i);
    float4 s2 = *(const float4*)(part + 2 * (size_t)total + i);
    float4 s3 = *(const float4*)(part + 3 * (size_t)total + i);
    int col = i % Nc;
    float4 r;
    r.x = ((s0.x + s1.x) + s2.x) + s3.x + b0[col]     + (b1 ? b1[col]     : 0.f);
    r.y = ((s0.y + s1.y) + s2.y) + s3.y + b0[col + 1] + (b1 ? b1[col + 1] : 0.f);
    r.z = ((s0.z + s1.z) + s2.z) + s3.z + b0[col + 2] + (b1 ? b1[col + 2] : 0.f);
    r.w = ((s0.w + s1.w) + s2.w) + s3.w + b0[col + 3] + (b1 ? b1[col + 3] : 0.f);
    *(float4*)(C + i) = r;
}

// ===== fp32 -> bf16 converts =====
__global__ void conv_bf16(const float* __restrict__ src, __nv_bfloat16* __restrict__ dst) {
    size_t i = ((size_t)blockIdx.x * 256 + threadIdx.x) * 8;
    float4 a = *(const float4*)(src + i), b = *(const float4*)(src + i + 4);
    uint4 o;
    o.x = pack_bf16(a.x, a.y); o.y = pack_bf16(a.z, a.w);
    o.z = pack_bf16(b.x, b.y); o.w = pack_bf16(b.z, b.w);
    *(uint4*)(dst + i) = o;
}
__global__ void conv_dual(const float* __restrict__ s0, __nv_bfloat16* __restrict__ d0,
                          const float* __restrict__ s1, __nv_bfloat16* __restrict__ d1,
                          int nblk0) {
    const float* src; __nv_bfloat16* dst; size_t base;
    if ((int)blockIdx.x < nblk0) { src = s0; dst = d0; base = (size_t)blockIdx.x; }
    else { src = s1; dst = d1; base = (size_t)(blockIdx.x - nblk0); }
    size_t i = (base * 256 + threadIdx.x) * 8;
    float4 a = *(const float4*)(src + i), b = *(const float4*)(src + i + 4);
    uint4 o;
    o.x = pack_bf16(a.x, a.y); o.y = pack_bf16(a.z, a.w);
    o.z = pack_bf16(b.x, b.y); o.w = pack_bf16(b.z, b.w);
    *(uint4*)(dst + i) = o;
}

// ===== tensor GEMM v5 (R15-validated): all-cp.async, 3-stage, KC=64, 128x256 =====
#define M5_STAGE 55296
#define M5_SMEM  (3 * M5_STAGE)

template <int MODE, int KDIM, int TOK>
__global__ __launch_bounds__(256, 1)
void mma5(const __nv_bfloat16* __restrict__ Ab, const __nv_bfloat16* __restrict__ Bb,
          const float* __restrict__ bias, const float* __restrict__ vvec,
          float* __restrict__ out, int Ncols) {
    extern __shared__ char smem[];
    const uint32_t sbu = smem_u32(smem);
    const int tid = threadIdx.x, lane = tid & 31, warp = tid >> 5;
    const int wm = warp >> 2, wn = warp & 3;
    const int n0 = blockIdx.x * 256;
    const long m0 = (long)blockIdx.y * 128;
    const int KT = KDIM / 64;

    float acc[4][8][4];
#pragma unroll
    for (int i = 0; i < 4; i++)
#pragma unroll
        for (int j = 0; j < 8; j++)
#pragma unroll
            for (int c = 0; c < 4; c++) acc[i][j][c] = 0.f;

    auto cpA = [&](int kt, int buf) {
        uint32_t base = sbu + buf * M5_STAGE;
#pragma unroll
        for (int i = 0; i < 4; i++) {
            int seg = tid + 256 * i;
            int row = seg >> 3, c = seg & 7;
            const __nv_bfloat16* src = Ab + (m0 + row) * (size_t)KDIM + kt * 64 + c * 8;
            CPA16(base + row * 144 + c * 16, src);
        }
    };
    auto cpB = [&](int kt, int buf) {
        uint32_t base = sbu + buf * M5_STAGE + 18432;
#pragma unroll
        for (int i = 0; i < 8; i++) {
            int seg = tid + 256 * i;
            int row = seg >> 3, c = seg & 7;
            int gr = n0 + row;
            if (MODE == 1 && gr >= Ncols) gr = 0;
            const __nv_bfloat16* src = Bb + (size_t)gr * KDIM + kt * 64 + c * 8;
            CPA16(base + row * 144 + c * 16, src);
        }
    };

    const uint32_t a_lds = sbu + (wm * 64 + (lane & 15)) * 144 + (lane >> 4) * 16;
    const uint32_t b_lds = sbu + 18432 + (wn * 64 + (lane & 15)) * 144 + (lane >> 4) * 16;

    auto compute = [&](int buf) {
        uint32_t ab = a_lds + buf * M5_STAGE, bb = b_lds + buf * M5_STAGE;
#pragma unroll
        for (int s = 0; s < 4; s++) {
            unsigned af[4][4], bfr[8][2];
#pragma unroll
            for (int mi = 0; mi < 4; mi++)
                LDSM4(af[mi][0], af[mi][1], af[mi][2], af[mi][3], ab + mi * 2304 + s * 32);
#pragma unroll
            for (int p = 0; p < 4; p++) {
                unsigned r0, r1, r2, r3;
                LDSM4(r0, r1, r2, r3, bb + p * 2304 + s * 32);
                bfr[2 * p][0] = r0; bfr[2 * p][1] = r2;
                bfr[2 * p + 1][0] = r1; bfr[2 * p + 1][1] = r3;
            }
#pragma unroll
            for (int mi = 0; mi < 4; mi++)
#pragma unroll
                for (int ni = 0; ni < 8; ni++)
                    mma16816(acc[mi][ni], af[mi], bfr[ni], acc[mi][ni]);
        }
    };

    cpA(0, 0); cpB(0, 0); CPA_COMMIT();
    if (KT > 1) { cpA(1, 1); cpB(1, 1); }
    CPA_COMMIT();

    for (int kt = 0; kt < KT; kt++) {
        CPA_WAIT1();
        __syncthreads();
        if (kt + 2 < KT) { cpA(kt + 2, (kt + 2) % 3); cpB(kt + 2, (kt + 2) % 3); }
        CPA_COMMIT();
        compute(kt % 3);
    }
    __syncthreads();

    if (MODE == 0) {
        float rs[4][2];
#pragma unroll
        for (int mi = 0; mi < 4; mi++) { rs[mi][0] = 0.f; rs[mi][1] = 0.f; }
#pragma unroll
        for (int mi = 0; mi < 4; mi++)
#pragma unroll
            for (int ni = 0; ni < 8; ni++)
#pragma unroll
                for (int c = 0; c < 4; c++) {
                    int col = wn * 64 + ni * 8 + (lane & 3) * 2 + (c & 1);
                    long r = m0 + wm * 64 + mi * 16 + (lane >> 2) + (c >> 1) * 8;
                    int bb2 = (int)(r / TOK);
                    float x = acc[mi][ni][c] + bias[(size_t)bb2 * Ncols + n0 + col];
                    x = fminf(fmaxf(x, -15.f), 15.f);
                    float e = __expf(2.f * x);
                    rs[mi][c >> 1] += __fdividef(e - 1.f, e + 1.f) * vvec[n0 + col];
                }
#pragma unroll
        for (int mi = 0; mi < 4; mi++)
#pragma unroll
            for (int h = 0; h < 2; h++) {
                rs[mi][h] += __shfl_xor_sync(0xffffffffu, rs[mi][h], 1);
                rs[mi][h] += __shfl_xor_sync(0xffffffffu, rs[mi][h], 2);
            }
        float* red = (float*)smem;
        if ((lane & 3) == 0) {
#pragma unroll
            for (int mi = 0; mi < 4; mi++)
#pragma unroll
                for (int h = 0; h < 2; h++) {
                    int rl = wm * 64 + mi * 16 + (lane >> 2) + h * 8;
                    red[rl * 4 + wn] = rs[mi][h];
                }
        }
        __syncthreads();
        if (tid < 128)
            out[(m0 + tid) * gridDim.x + blockIdx.x] =
                red[tid * 4] + red[tid * 4 + 1] + red[tid * 4 + 2] + red[tid * 4 + 3];
    } else {
#pragma unroll
        for (int mi = 0; mi < 4; mi++)
#pragma unroll
            for (int ni = 0; ni < 8; ni++)
#pragma unroll
                for (int c = 0; c < 4; c++) {
                    int gcol = n0 + wn * 64 + ni * 8 + (lane & 3) * 2 + (c & 1);
                    long r = m0 + wm * 64 + mi * 16 + (lane >> 2) + (c >> 1) * 8;
                    if (gcol < Ncols)
                        out[(size_t)r * Ncols + gcol] = acc[mi][ni][c] + bias[gcol];
                }
    }
}

// ===== elementwise / reductions =====
__global__ void lstm_kernel(const float* __restrict__ dec_c,
                            float* __restrict__ o_h, float* __restrict__ o_c) {
    int idx = blockIdx.x * 256 + threadIdx.x;
    int b = idx >> 9, h = idx & 511;
    const float* g = g_gates + (size_t)b * 2048;
    float c  = sigm(g[512 + h]) * dec_c[idx] + sigm(g[h]) * tanhf(g[1024 + h]);
    float hn = sigm(g[1536 + h]) * tanhf(c);
    o_h[idx] = hn; o_c[idx] = c;
    g_sthat[(size_t)b * 1024 + h] = hn;
    g_sthat[(size_t)b * 1024 + 512 + h] = c;
}

__global__ void et_finalize(const float* __restrict__ sumt, const float* __restrict__ mask,
                            float* __restrict__ o_sum) {
    int b = blockIdx.x, n = threadIdx.x;   // 512 thr
    __shared__ float sh[512];
    float atv = 0.f;
    if (n < N_) {
        const float* p = g_et_part + (size_t)(b * N_ + n) * 4;
        float e = expf(p[0] + p[1] + p[2] + p[3]);
        float st = sumt[b * N_ + n];
        o_sum[b * N_ + n] = st + e;
        atv = (e / st) * mask[b * N_ + n];
    }
    sh[n] = atv; __syncthreads();
    for (int st = 256; st > 0; st >>= 1) { if (n < st) sh[n] += sh[n + st]; __syncthreads(); }
    if (n < N_) g_at[b * N_ + n] = atv / sh[0];
}

__global__ void ctx_enc(const float* __restrict__ enc, float* __restrict__ o_cte) {
    int b = blockIdx.x, t = threadIdx.x;   // 256 thr
    __shared__ float a_s[N_];
    for (int i = t; i < N_; i += 256) a_s[i] = g_at[b * N_ + i];
    __syncthreads();
    float4 acc = make_float4(0, 0, 0, 0);
    const float4* base = (const float4*)(enc + (size_t)b * N_ * 1024) + t;
#pragma unroll 4
    for (int n = 0; n < N_; ++n) {
        float4 v = base[(size_t)n * 256]; float w = a_s[n];
        acc.x += w * v.x; acc.y += w * v.y; acc.z += w * v.z; acc.w += w * v.w;
    }
    ((float4*)(o_cte + (size_t)b * 1024))[t] = acc;
}

__global__ void dec_attn_finalize(const float* __restrict__ prev_s,
                                  const float* __restrict__ h_new,
                                  float* __restrict__ o_prev) {
    int b = blockIdx.x, tid = threadIdx.x;  // 256 thr
    __shared__ float atd[T_];
    __shared__ float tot;
    if (tid < T_) {
        const float* p = g_etd_part + (size_t)(b * T_ + tid) * 2;
        atd[tid] = expf(p[0] + p[1]);
    }
    __syncthreads();
    if (tid == 0) { float s = 0.f; for (int i = 0; i < T_; ++i) s += atd[i]; tot = s; }
    __syncthreads();
    float inv = 1.f / tot;
#pragma unroll
    for (int cg = 0; cg < 2; ++cg) {
        int col = tid + cg * 256;
        float acc = 0.f;
        for (int t2 = 0; t2 < T_; ++t2)
            acc += atd[t2] * prev_s[((size_t)b * T_ + t2) * H_ + col];
        g_ctd[(size_t)b * H_ + col] = acc * inv;
    }
    for (int i = tid; i < T_ * H_; i += 256)
        o_prev[(size_t)b * (T_ + 1) * H_ + i] = prev_s[(size_t)b * T_ * H_ + i];
    for (int i = tid; i < H_; i += 256)
        o_prev[(size_t)b * (T_ + 1) * H_ + T_ * H_ + i] = h_new[(size_t)b * H_ + i];
}

__global__ void pgen_kernel(const float* __restrict__ cte,
                            const float* __restrict__ w, const float* __restrict__ bias) {
    int b = blockIdx.x, tid = threadIdx.x;  // 256 thr, K=2816
    float s = 0.f;
    for (int k = tid; k < 2816; k += 256) {
        float a;
        if (k < 1024)      a = cte[(size_t)b * 1024 + k];
        else if (k < 1536) a = g_ctd[(size_t)b * 512 + (k - 1024)];
        else if (k < 2560) a = g_sthat[(size_t)b * 1024 + (k - 1536)];
        else               a = g_x[(size_t)b * 256 + (k - 2560)];
        s += a * w[k];
    }
    __shared__ float sh[256];
    sh[tid] = s; __syncthreads();
    for (int st = 128; st > 0; st >>= 1) { if (tid < st) sh[tid] += sh[tid + st]; __syncthreads(); }
    if (tid == 0) g_pgen[b] = sigm(sh[0] + bias[0]);
}

__global__ void vocab_stats() {
    int b = blockIdx.x, tid = threadIdx.x;  // 512 thr
    const float* row = g_logits + (size_t)b * V_;
    __shared__ float sh[512];
    float m = -1e30f;
    for (int v = tid; v < V_; v += 512) m = fmaxf(m, row[v]);
    sh[tid] = m; __syncthreads();
    for (int st = 256; st > 0; st >>= 1) { if (tid < st) sh[tid] = fmaxf(sh[tid], sh[tid + st]); __syncthreads(); }
    float mx = sh[0]; __syncthreads();
    float s = 0.f;
    for (int v = tid; v < V_; v += 512) s += expf(row[v] - mx);
    sh[tid] = s; __syncthreads();
    for (int st = 256; st > 0; st >>= 1) { if (tid < st) sh[tid] += sh[tid + st]; __syncthreads(); }
    if (tid == 0) { g_rmax[b] = mx; g_rsum[b] = sh[0]; }
}

__global__ void final_dist_kernel(const int* __restrict__ idx, float* __restrict__ out) {
    int b = blockIdx.x, tid = threadIdx.x;  // 512 thr
    float pg = g_pgen[b], scale = pg / g_rsum[b], mx = g_rmax[b];
    float* row = out + (size_t)b * (V_ + OOV_);
    const float* lrow = g_logits + (size_t)b * V_;
    for (int v = tid; v < V_ + OOV_; v += 512)
        row[v] = (v < V_) ? expf(lrow[v] - mx) * scale : 0.f;
    __shared__ int   sidx[N_];
    __shared__ float sval[N_];
    float am = 1.f - pg;
    for (int n = tid; n < N_; n += 512) {
        sidx[n] = idx[b * N_ + n];
        sval[n] = am * g_at[b * N_ + n];
    }
    __syncthreads();
    if (tid < N_) {
        int my = sidx[tid];
        bool leader = true;
        for (int i = 0; i < tid; ++i) if (sidx[i] == my) { leader = false; break; }
        if (leader) {
            float s = 0.f;
            for (int i = tid; i < N_; ++i) if (sidx[i] == my) s += sval[i];
            row[my] += s;
        }
    }
}

// ===== host launcher =====
extern "C" void kernel_launch(void* const* d_in, const int* in_sizes, int n_in,
                              void* d_out, int out_size) {
    (void)in_sizes; (void)n_in; (void)out_size;
    const float* x_t       = (const float*)d_in[0];
    const float* dec_h     = (const float*)d_in[1];
    const float* dec_c     = (const float*)d_in[2];
    const float* enc_out   = (const float*)d_in[3];
    const float* enc_mask  = (const float*)d_in[4];
    const float* ct_e      = (const float*)d_in[5];
    const int*   ext_vocab = (const int*)  d_in[7];
    const float* sum_temp  = (const float*)d_in[8];
    const float* prev_s    = (const float*)d_in[9];
    const float* xw   = (const float*)d_in[10];
    const float* xb   = (const float*)d_in[11];
    const float* wih  = (const float*)d_in[12];
    const float* whh  = (const float*)d_in[13];
    const float* bih  = (const float*)d_in[14];
    const float* bhh  = (const float*)d_in[15];
    const float* pgw  = (const float*)d_in[16];
    const float* pgb  = (const float*)d_in[17];
    const float* Vw   = (const float*)d_in[18];
    const float* Vb   = (const float*)d_in[19];
    const float* V1w  = (const float*)d_in[20];
    const float* V1b  = (const float*)d_in[21];
    const float* Whw  = (const float*)d_in[22];
    const float* Wsw  = (const float*)d_in[23];
    const float* Wsb  = (const float*)d_in[24];
    const float* vw   = (const float*)d_in[25];
    const float* Wpw  = (const float*)d_in[26];
    const float* Wsdw = (const float*)d_in[27];
    const float* Wsdb = (const float*)d_in[28];
    const float* vdw  = (const float*)d_in[29];

    float* out = (float*)d_out;
    float* o_fd   = out;
    float* o_h    = out + (size_t)B_ * (V_ + OOV_);
    float* o_c    = o_h  + B_ * H_;
    float* o_cte  = o_c  + B_ * H_;
    float* o_sum  = o_cte + B_ * 2 * H_;
    float* o_prev = o_sum + B_ * N_;

    void* p;
    cudaGetSymbolAddress(&p, g_x);        float* px   = (float*)p;
    cudaGetSymbolAddress(&p, g_gates);    float* pg   = (float*)p;
    cudaGetSymbolAddress(&p, g_sthat);    float* pst  = (float*)p;
    cudaGetSymbolAddress(&p, g_bias_e);   float* pbe  = (float*)p;
    cudaGetSymbolAddress(&p, g_bias_d);   float* pbd  = (float*)p;
    cudaGetSymbolAddress(&p, g_et_part);  float* pet  = (float*)p;
    cudaGetSymbolAddress(&p, g_etd_part); float* petd = (float*)p;
    cudaGetSymbolAddress(&p, g_ctd);      float* pctd = (float*)p;
    cudaGetSymbolAddress(&p, g_outfeat);  float* pof  = (float*)p;
    cudaGetSymbolAddress(&p, g_logits);   float* plg  = (float*)p;
    cudaGetSymbolAddress(&p, g_part);     float* ppart = (float*)p;
    cudaGetSymbolAddress(&p, g_abf);      __nv_bfloat16* pab = (__nv_bfloat16*)p;
    cudaGetSymbolAddress(&p, g_bbf);      __nv_bfloat16* pbb = (__nv_bfloat16*)p;
    cudaGetSymbolAddress(&p, g_wpbf);     __nv_bfloat16* pwp = (__nv_bfloat16*)p;
    cudaGetSymbolAddress(&p, g_psbf);     __nv_bfloat16* pps = (__nv_bfloat16*)p;
    cudaGetSymbolAddress(&p, g_ofbf);     __nv_bfloat16* pob = (__nv_bfloat16*)p;
    cudaGetSymbolAddress(&p, g_v1bf);     __nv_bfloat16* pv1 = (__nv_bfloat16*)p;
    const float* nf = nullptr;

    cudaFuncSetAttribute((const void*)mma5<0, 1024, 400>, cudaFuncAttributeMaxDynamicSharedMemorySize, M5_SMEM);
    cudaFuncSetAttribute((const void*)mma5<0, 512, 49>,   cudaFuncAttributeMaxDynamicSharedMemorySize, M5_SMEM);
    cudaFuncSetAttribute((const void*)mma5<1, 512, 1>,    cudaFuncAttributeMaxDynamicSharedMemorySize, M5_SMEM);

    // 0. x = cat(x_t, ct_e) @ xw^T + xb           [256,256] K=1280, split-K 4x320
    sgemm3<<<dim3(4, 4, 4), 256>>>(x_t, E_, ct_e, 2 * H_, nf, 0,
                                   xw, 1280, nf, 0, ppart, 256, 256, 320);
    reduce4<<<64, 256>>>(ppart, xb, nf, px, 256, 65536);
    // 1. gates = cat(x, dec_h) @ cat(wih|whh)^T   [256,2048] K=768, split-K 4x192
    sgemm3<<<dim3(32, 4, 4), 256>>>(px, 256, dec_h, 512, nf, 0,
                                    wih, 256, whh, 512, ppart, 256, 2048, 192);
    reduce4<<<512, 256>>>(ppart, bih, bhh, pg, 2048, 524288);
    // 2. LSTM
    lstm_kernel<<<B_ * H_ / 256, 256>>>(dec_c, o_h, o_c);
    // 3. bias_e = st_hat @ Ws^T + Ws_b            [256,1024] K=1024, split-K 4x256
    sgemm3<<<dim3(16, 4, 4), 256>>>(pst, 1024, nf, 0, nf, 0,
                                    Wsw, 1024, nf, 0, ppart, 256, 1024, 256);
    reduce4<<<256, 256>>>(ppart, Wsb, nf, pbe, 1024, 262144);
    // 4. enc_out + Whw -> bf16
    conv_dual<<<51712, 256>>>(enc_out, pab, Whw, pbb, 51200);
    // 5. encoder attention scores (tensor GEMM, fused tanh*v)
    mma5<0, 1024, 400><<<dim3(4, 800), 256, M5_SMEM>>>(pab, pbb, pbe, vw, pet, 1024);
    // 6-8. smaller converts
    conv_bf16<<<128, 256>>>(Wpw, pwp);
    conv_bf16<<<3136, 256>>>(prev_s, pps);
    conv_bf16<<<12500, 256>>>(V1w, pv1);
    // 9. temporal softmax
    et_finalize<<<B_, 512>>>(sum_temp, enc_mask, o_sum);
    // 10. ct_e_new (fp32 enc_out — exact)
    ctx_enc<<<B_, 256>>>(enc_out, o_cte);
    // 11. bias_d = h_new @ Wsd^T + Wsd_b          [256,512] K=512, split-K 4x128
    sgemm3<<<dim3(8, 4, 4), 256>>>(o_h, 512, nf, 0, nf, 0,
                                   Wsdw, 512, nf, 0, ppart, 256, 512, 128);
    reduce4<<<128, 256>>>(ppart, Wsdb, nf, pbd, 512, 131072);
    // 12. decoder attention scores
    mma5<0, 512, 49><<<dim3(2, 98), 256, M5_SMEM>>>(pps, pwp, pbd, vdw, petd, 512);
    // 13. ct_d + prev_s_new
    dec_attn_finalize<<<B_, 256>>>(prev_s, o_h, o_prev);
    // 14. p_gen
    pgen_kernel<<<B_, 256>>>(o_cte, pgw, pgb);
    // 15. outfeat = cat(h,cte,ctd) @ V^T + Vb     [256,512] K=2048, split-K 4x512
    sgemm3<<<dim3(8, 4, 4), 256>>>(o_h, 512, o_cte, 1024, pctd, 512,
                                   Vw, 2048, nf, 0, ppart, 256, 512, 512);
    reduce4<<<128, 256>>>(ppart, Vb, nf, pof, 512, 131072);
    // 16-17. outfeat -> bf16, logits
    conv_bf16<<<64, 256>>>(pof, pob);
    mma5<1, 512, 1><<<dim3(196, 2), 256, M5_SMEM>>>(pob, pv1, V1b, nf, plg, V_);
    // 18-19. softmax + final dist
    vocab_stats<<<B_, 512>>>();
    final_dist_kernel<<<B_, 512>>>(ext_vocab, o_fd);
}